// round 5
// baseline (speedup 1.0000x reference)
#include <cuda_runtime.h>
#include <math.h>
#include <cstdint>

#define BB 4096
#define NN 32
#define HH 256
#define RR 3
#define VDECAY 0.7f
#define CHS 260

typedef unsigned long long ull;

// ---------------- device scratch ----------------
__device__ float g_WfTi[RR * 128 * HH * 2];   // [r][h2][g]{h even, h odd}
__device__ float g_WgT[3 * 512 * HH];         // [gate][k][g]
__device__ float g_comb[BB * 512];            // [b][input | child_h_sum]
__device__ float g_csum[BB * HH];

// ---------------- helpers ----------------
__device__ __forceinline__ ull pk2(float a, float b) {
    ull r; asm("mov.b64 %0, {%1, %2};" : "=l"(r) : "f"(a), "f"(b)); return r;
}
__device__ __forceinline__ float2 upk2(ull v) {
    float2 r; asm("mov.b64 {%0, %1}, %2;" : "=f"(r.x), "=f"(r.y) : "l"(v)); return r;
}
__device__ __forceinline__ ull fma2_(ull a, ull b, ull c) {
    ull d; asm("fma.rn.f32x2 %0, %1, %2, %3;" : "=l"(d) : "l"(a), "l"(b), "l"(c)); return d;
}
__device__ __forceinline__ void cpa16(void* sdst, const void* gsrc) {
    unsigned s = (unsigned)__cvta_generic_to_shared(sdst);
    asm volatile("cp.async.ca.shared.global [%0], [%1], 16;" :: "r"(s), "l"(gsrc) : "memory");
}
__device__ __forceinline__ void cpa_commit() { asm volatile("cp.async.commit_group;" ::: "memory"); }
template <int N> __device__ __forceinline__ void cpa_wait() {
    asm volatile("cp.async.wait_group %0;" :: "n"(N) : "memory");
}

// ---------------- prep: W_f pair-interleave + gate transpose ----------------
__global__ void prep_kernel(const float* __restrict__ Wf,
                            const float* __restrict__ Wi,
                            const float* __restrict__ Wo,
                            const float* __restrict__ Wu) {
    int idx = blockIdx.x * blockDim.x + threadIdx.x;
    const int NF2 = RR * 128 * HH;   // 98304 float2 slots
    const int NG  = 3 * 512 * HH;    // 393216
    if (idx < NF2) {
        int g  = idx & 255;
        int h2 = (idx >> 8) & 127;
        int r  = idx >> 15;
        float2 v = *(const float2*)&Wf[(r * HH + g) * HH + 2 * h2];
        *(float2*)&g_WfTi[idx * 2] = v;
    } else if (idx < NF2 + NG) {
        int j = idx - NF2;
        int g = j & 255;
        int t = j >> 8;
        int k = t & 511;
        int gate = t >> 9;
        const float* W = (gate == 0) ? Wi : ((gate == 1) ? Wo : Wu);
        g_WgT[j] = W[g * 512 + k];
    }
}

// ---------------- tree kernel: 2 batches/block ----------------
// dyn smem: sh_ch [0,66560) = 64 x 260 floats; sh_facc [66560,132096) = 64 x 256
#define T_SMEM 132096

__global__ __launch_bounds__(256) void tree_kernel(
    const float* __restrict__ input_vec,
    const float* __restrict__ child_h,
    const float* __restrict__ child_c,
    const int*   __restrict__ relation_ids,
    const int*   __restrict__ virtual_mask,
    const float* __restrict__ rel_emb,
    const float* __restrict__ b_f,
    const float* __restrict__ w_att,
    const float* __restrict__ b_att)
{
    extern __shared__ float sm[];
    float* sh_ch   = sm;             // [64][CHS]
    float* sh_facc = sm + 64 * CHS;  // [64][256], column g private to thread g

    __shared__ int   sh_rid[64], sh_perm[64], sh_srid[64];
    __shared__ int   sh_bounds[2][4];
    __shared__ float sh_decay[64], sh_sdecay[64], sh_score[64], sh_attn[64];

    const int b0   = blockIdx.x * 2;
    const int tid  = threadIdx.x;
    const int lane = tid & 31;
    const int warp = tid >> 5;
    const int g    = tid;

    if (tid < 64) {
        sh_rid[tid]   = relation_ids[b0 * NN + tid];
        sh_decay[tid] = virtual_mask[b0 * NN + tid] ? VDECAY : 1.0f;
    }
    __syncthreads();

    // per-batch counting sort by relation
    if (tid < 2) {
        int base = tid * 32;
        int cnt[3] = {0, 0, 0};
        for (int n = 0; n < 32; n++) cnt[sh_rid[base + n]]++;
        int off[3];
        off[0] = 0; off[1] = cnt[0]; off[2] = cnt[0] + cnt[1];
        sh_bounds[tid][0] = base;
        sh_bounds[tid][1] = base + off[1];
        sh_bounds[tid][2] = base + off[2];
        sh_bounds[tid][3] = base + 32;
        for (int n = 0; n < 32; n++) {
            int r = sh_rid[base + n];
            int p = base + off[r]++;
            sh_perm[p]   = n;
            sh_srid[p]   = r;
            sh_sdecay[p] = sh_decay[base + n];
        }
    }
    __syncthreads();

    // load decayed child_h (sorted order)
    for (int idx = tid; idx < 64 * HH; idx += 256) {
        int p = idx >> 8, h = idx & 255;
        int beta = p >> 5;
        sh_ch[p * CHS + h] =
            child_h[((size_t)(b0 + beta) * NN + sh_perm[p]) * HH + h] * sh_sdecay[p];
    }
    __syncthreads();

    // attention scores: each warp 8 children
    {
        float batt = b_att[0];
        #pragma unroll
        for (int c = 0; c < 8; c++) {
            int p = warp * 8 + c;
            int r = sh_srid[p];
            float s = 0.0f;
            #pragma unroll
            for (int j = 0; j < 8; j++) {
                int h = j * 32 + lane;
                s = fmaf(rel_emb[r * HH + h] + sh_ch[p * CHS + h], w_att[h], s);
            }
            #pragma unroll
            for (int off = 16; off; off >>= 1) s += __shfl_xor_sync(0xffffffffu, s, off);
            if (lane == 0) sh_score[p] = s + batt;
        }
    }
    __syncthreads();

    if (warp < 2) {  // softmax per batch
        float v = sh_score[warp * 32 + lane], m = v;
        #pragma unroll
        for (int off = 16; off; off >>= 1) m = fmaxf(m, __shfl_xor_sync(0xffffffffu, m, off));
        float e = expf(v - m), s = e;
        #pragma unroll
        for (int off = 16; off; off >>= 1) s += __shfl_xor_sync(0xffffffffu, s, off);
        sh_attn[warp * 32 + lane] = e / s;
    }
    __syncthreads();

    // comb = [input | child_h_sum]
    #pragma unroll
    for (int beta = 0; beta < 2; beta++) {
        float hs = 0.0f;
        #pragma unroll
        for (int q = 0; q < 32; q++) {
            int p = beta * 32 + q;
            hs = fmaf(sh_attn[p], sh_ch[p * CHS + g], hs);
        }
        g_comb[(size_t)(b0 + beta) * 512 + 256 + g] = hs;
        g_comb[(size_t)(b0 + beta) * 512 + g] = input_vec[(size_t)(b0 + beta) * HH + g];
    }

    // facc zero (column g private — no sync needed)
    #pragma unroll
    for (int p = 0; p < 64; p++) sh_facc[p * 256 + g] = 0.0f;

    // f-matvec: packed f32x2, weights register-cached per (r, hb)
    for (int r = 0; r < RR; r++) {
        int a0 = sh_bounds[0][r], a1 = sh_bounds[0][r + 1];
        int c0 = sh_bounds[1][r], c1 = sh_bounds[1][r + 1];
        if (a0 == a1 && c0 == c1) continue;
        #pragma unroll 1
        for (int hb = 0; hb < 8; hb++) {
            ull w[16];
            #pragma unroll
            for (int j = 0; j < 16; j++)
                w[j] = *(const ull*)&g_WfTi[(((r * 128) + hb * 16 + j) * 256 + g) * 2];
            for (int seg = 0; seg < 2; seg++) {
                int p  = seg ? c0 : a0;
                int pe = seg ? c1 : a1;
                for (; p < pe; ++p) {
                    const ulonglong2* cp2 = (const ulonglong2*)&sh_ch[p * CHS + hb * 32];
                    ull a = 0ull;
                    #pragma unroll
                    for (int j2 = 0; j2 < 8; j2++) {
                        ulonglong2 cv = cp2[j2];
                        a = fma2_(cv.x, w[2 * j2], a);
                        a = fma2_(cv.y, w[2 * j2 + 1], a);
                    }
                    float2 f2 = upk2(a);
                    sh_facc[p * 256 + g] += f2.x + f2.y;
                }
            }
        }
    }

    // child_c_sum
    const float bf0 = b_f[g], bf1 = b_f[256 + g], bf2 = b_f[512 + g];
    #pragma unroll
    for (int beta = 0; beta < 2; beta++) {
        float cs = 0.0f;
        for (int q = 0; q < 32; q++) {
            int p = beta * 32 + q;
            int r = sh_srid[p];
            float bfv = (r == 0) ? bf0 : ((r == 1) ? bf1 : bf2);
            float cc = child_c[((size_t)(b0 + beta) * NN + sh_perm[p]) * HH + g] * sh_sdecay[p];
            cs = fmaf(sh_facc[p * 256 + g] + bfv, cc, cs);
        }
        g_csum[(size_t)(b0 + beta) * HH + g] = cs;
    }
}

// ---------------- gates kernel: packed comb + cp.async weight staging ----------------
// dyn smem: sh_cp ull[4096] [0,32768); sh_w float[2][6144] [32768, 81920)
#define G_SMEM 81920

__global__ __launch_bounds__(256) void gates_kernel(
    const float* __restrict__ b_i,
    const float* __restrict__ b_o,
    const float* __restrict__ b_u,
    float* __restrict__ out)
{
    extern __shared__ char gsm[];
    ull*   sh_cp = (ull*)gsm;                 // [k][bp] packed batch pairs
    float* sh_w  = (float*)(gsm + 32768);     // [2][gate*2048 + kk*256 + g]

    const int b0  = blockIdx.x * 16;
    const int tid = threadIdx.x;
    const int g   = tid;

    // pack comb pairs once
    for (int idx = tid; idx < 8 * 512; idx += 256) {
        int k = idx & 511, bp = idx >> 9;
        float a = g_comb[(size_t)(b0 + 2 * bp) * 512 + k];
        float c = g_comb[(size_t)(b0 + 2 * bp + 1) * 512 + k];
        sh_cp[k * 8 + bp] = pk2(a, c);
    }

    auto stage = [&](int c, int buf) {
        float* dst = sh_w + buf * 6144;
        for (int i = tid; i < 1536; i += 256) {
            int j = i * 4;
            int g4 = j & 255, kk = (j >> 8) & 7, gate = j >> 11;
            cpa16(dst + j, &g_WgT[((size_t)gate * 512 + c * 8 + kk) * 256 + g4]);
        }
        cpa_commit();
    };

    ull ai[8], ao[8], au[8];
    #pragma unroll
    for (int bp = 0; bp < 8; bp++) { ai[bp] = 0ull; ao[bp] = 0ull; au[bp] = 0ull; }

    stage(0, 0);
    __syncthreads();   // sh_cp ready

    #pragma unroll 1
    for (int c = 0; c < 64; c++) {
        int buf = c & 1;
        if (c < 63) stage(c + 1, buf ^ 1);
        else cpa_commit();
        cpa_wait<1>();
        __syncthreads();
        const float* wb = sh_w + buf * 6144;
        #pragma unroll
        for (int kk = 0; kk < 8; kk++) {
            int k = c * 8 + kk;
            float wiv = wb[kk * 256 + g];
            float wov = wb[2048 + kk * 256 + g];
            float wuv = wb[4096 + kk * 256 + g];
            ull wi2 = pk2(wiv, wiv), wo2 = pk2(wov, wov), wu2 = pk2(wuv, wuv);
            #pragma unroll
            for (int bp = 0; bp < 8; bp++) {
                ull cp = sh_cp[k * 8 + bp];
                ai[bp] = fma2_(cp, wi2, ai[bp]);
                ao[bp] = fma2_(cp, wo2, ao[bp]);
                au[bp] = fma2_(cp, wu2, au[bp]);
            }
        }
        __syncthreads();
    }
    cpa_wait<0>();

    const float biv = b_i[g], bov = b_o[g], buv = b_u[g];
    #pragma unroll
    for (int bp = 0; bp < 8; bp++) {
        float2 fi = upk2(ai[bp]);
        float2 fo = upk2(ao[bp]);
        float2 fu = upk2(au[bp]);
        #pragma unroll
        for (int s = 0; s < 2; s++) {
            int b = b0 + 2 * bp + s;
            float av = s ? fi.y : fi.x;
            float bv = s ? fo.y : fo.x;
            float uvp = s ? fu.y : fu.x;
            float cs = g_csum[(size_t)b * HH + g];
            float iv = 1.0f / (1.0f + expf(-(av + biv)));
            float ov = 1.0f / (1.0f + expf(-(bv + bov)));
            float uv = tanhf(uvp + buv);
            float cc = fmaf(iv, uv, cs);
            float hh = ov * tanhf(cc);
            out[(size_t)b * HH + g]            = hh;  // h first
            out[(size_t)(BB + b) * HH + g]     = cc;  // then c
        }
    }
}

// ---------------- launch ----------------
extern "C" void kernel_launch(void* const* d_in, const int* in_sizes, int n_in,
                              void* d_out, int out_size) {
    const float* input_vec = (const float*)d_in[0];
    const float* child_h   = (const float*)d_in[1];
    const float* child_c   = (const float*)d_in[2];
    const int*   rid       = (const int*)d_in[3];
    const int*   vmask     = (const int*)d_in[4];
    const float* rel_emb   = (const float*)d_in[5];
    const float* W_i = (const float*)d_in[6];
    const float* b_i = (const float*)d_in[7];
    const float* W_f = (const float*)d_in[8];
    const float* b_f = (const float*)d_in[9];
    const float* W_o = (const float*)d_in[10];
    const float* b_o = (const float*)d_in[11];
    const float* W_u = (const float*)d_in[12];
    const float* b_u = (const float*)d_in[13];
    const float* w_att = (const float*)d_in[14];
    const float* b_att = (const float*)d_in[15];
    float* out = (float*)d_out;

    cudaFuncSetAttribute(tree_kernel,  cudaFuncAttributeMaxDynamicSharedMemorySize, T_SMEM);
    cudaFuncSetAttribute(gates_kernel, cudaFuncAttributeMaxDynamicSharedMemorySize, G_SMEM);

    prep_kernel<<<1921, 256>>>(W_f, W_i, W_o, W_u);
    tree_kernel<<<BB / 2, 256, T_SMEM>>>(input_vec, child_h, child_c, rid, vmask,
                                         rel_emb, b_f, w_att, b_att);
    gates_kernel<<<BB / 16, 256, G_SMEM>>>(b_i, b_o, b_u, out);
}

// round 9
// speedup vs baseline: 1.3775x; 1.3775x over previous
#include <cuda_runtime.h>
#include <cuda_bf16.h>
#include <cstdint>
#include <math.h>

#define BB 4096
#define NN 32
#define HH 256
#define RR 3
#define VDECAY 0.7f

// ---------------- device scratch ----------------
__device__ float g_WgT[3 * 512 * HH];      // [gate][k][g]
__device__ float g_comb[BB * 512];         // [b][input | child_h_sum]
__device__ float g_csum3[RR * BB * HH];    // per-relation partial csum

// ---------------- helpers ----------------
__device__ __forceinline__ uint32_t smem_u32(const void* p) {
    uint32_t a;
    asm("{ .reg .u64 t; cvta.to.shared.u64 t, %1; cvt.u32.u64 %0, t; }" : "=r"(a) : "l"(p));
    return a;
}
__device__ __forceinline__ void ldsm4(uint32_t* r, uint32_t addr) {
    asm volatile("ldmatrix.sync.aligned.m8n8.x4.shared.b16 {%0,%1,%2,%3}, [%4];"
                 : "=r"(r[0]), "=r"(r[1]), "=r"(r[2]), "=r"(r[3]) : "r"(addr));
}
__device__ __forceinline__ void mma16816(float* d, const uint32_t* a, const uint32_t* b) {
    asm volatile("mma.sync.aligned.m16n8k16.row.col.f32.bf16.bf16.f32 "
                 "{%0,%1,%2,%3},{%4,%5,%6,%7},{%8,%9},{%0,%1,%2,%3};"
                 : "+f"(d[0]), "+f"(d[1]), "+f"(d[2]), "+f"(d[3])
                 : "r"(a[0]), "r"(a[1]), "r"(a[2]), "r"(a[3]), "r"(b[0]), "r"(b[1]));
}
__device__ __forceinline__ uint32_t pkbf(float x, float y) {
    __nv_bfloat162 t = __floats2bfloat162_rn(x, y);
    return *(uint32_t*)&t;
}
__device__ __forceinline__ void cpa16(void* sdst, const void* gsrc) {
    unsigned s = (unsigned)__cvta_generic_to_shared(sdst);
    asm volatile("cp.async.ca.shared.global [%0], [%1], 16;" :: "r"(s), "l"(gsrc) : "memory");
}
#define CPA_COMMIT() asm volatile("cp.async.commit_group;" ::: "memory")
template <int N> __device__ __forceinline__ void cpa_wait() {
    asm volatile("cp.async.wait_group %0;" :: "n"(N) : "memory");
}

// ---------------- prep: gate weight transpose ----------------
__global__ void prep_kernel(const float* __restrict__ Wi,
                            const float* __restrict__ Wo,
                            const float* __restrict__ Wu) {
    int idx = blockIdx.x * blockDim.x + threadIdx.x;
    if (idx < 3 * 512 * HH) {
        int g = idx & 255, t = idx >> 8, k = t & 511, gate = t >> 9;
        const float* W = (gate == 0) ? Wi : ((gate == 1) ? Wo : Wu);
        g_WgT[idx] = W[g * 512 + k];
    }
}

// ---------------- attention + comb (validated) ----------------
#define CHS 260
__global__ __launch_bounds__(256) void attn_kernel(
    const float* __restrict__ input_vec, const float* __restrict__ child_h,
    const int* __restrict__ relation_ids, const int* __restrict__ virtual_mask,
    const float* __restrict__ rel_emb, const float* __restrict__ w_att,
    const float* __restrict__ b_att)
{
    __shared__ float sh_ch[NN * CHS];
    __shared__ int   sh_rid[NN];
    __shared__ float sh_decay[NN], sh_score[NN], sh_attn[NN];
    const int b = blockIdx.x, tid = threadIdx.x, lane = tid & 31, warp = tid >> 5;

    if (tid < NN) {
        sh_rid[tid]   = relation_ids[b * NN + tid];
        sh_decay[tid] = virtual_mask[b * NN + tid] ? VDECAY : 1.0f;
    }
    __syncthreads();
    {
        const float* chb = child_h + (size_t)b * NN * HH;
        for (int idx = tid; idx < NN * HH; idx += 256) {
            int n = idx >> 8, h = idx & 255;
            sh_ch[n * CHS + h] = chb[n * HH + h] * sh_decay[n];
        }
    }
    __syncthreads();
    {
        float batt = b_att[0];
        #pragma unroll
        for (int c = 0; c < 4; c++) {
            int p = warp * 4 + c;
            int r = sh_rid[p];
            float s = 0.0f;
            #pragma unroll
            for (int j = 0; j < 8; j++) {
                int h = j * 32 + lane;
                s = fmaf(rel_emb[r * HH + h] + sh_ch[p * CHS + h], w_att[h], s);
            }
            #pragma unroll
            for (int off = 16; off; off >>= 1) s += __shfl_xor_sync(0xffffffffu, s, off);
            if (lane == 0) sh_score[p] = s + batt;
        }
    }
    __syncthreads();
    if (warp == 0) {
        float v = sh_score[lane], m = v;
        #pragma unroll
        for (int off = 16; off; off >>= 1) m = fmaxf(m, __shfl_xor_sync(0xffffffffu, m, off));
        float e = expf(v - m), s = e;
        #pragma unroll
        for (int off = 16; off; off >>= 1) s += __shfl_xor_sync(0xffffffffu, s, off);
        sh_attn[lane] = e / s;
    }
    __syncthreads();
    const int g = tid;
    float hs = 0.0f;
    #pragma unroll
    for (int p = 0; p < NN; p++) hs = fmaf(sh_attn[p], sh_ch[p * CHS + g], hs);
    g_comb[b * 512 + 256 + g] = hs;
    g_comb[b * 512 + g]       = input_vec[(size_t)b * HH + g];
}

// ---------------- fgemm_mma: split-bf16 mma.sync f-matvec ----------------
// grid (256, 3, 2). block 256 = 8 warps.
// dyn smem: Bhi[128][264]bf16, Blo, Ahi[32][264]bf16, Alo, F[32][130]f32
#define BHI 0
#define BLO 67584
#define AHI 135168
#define ALO 152064
#define FSM 168960
#define FG_DYN 185600
#define BSTR 264
#define FSTR 130

__global__ __launch_bounds__(256) void fgemm_mma(
    const float* __restrict__ child_h,
    const float* __restrict__ child_c,
    const int*   __restrict__ relation_ids,
    const int*   __restrict__ virtual_mask,
    const float* __restrict__ W_f,
    const float* __restrict__ b_f)
{
    extern __shared__ char dsm[];
    __shared__ int   sList[512], sStart[17], sCnt[16];
    __shared__ float shCS[2][16][129];

    const int tid = threadIdx.x, lane = tid & 31, warp = tid >> 5;
    const int b0 = blockIdx.x * 16, r = blockIdx.y, g0 = blockIdx.z * 128;

    // compaction: counts -> prefix -> ordered fill
    if (tid < 16) {
        int c = 0;
        for (int n = 0; n < 32; n++) c += (relation_ids[(b0 + tid) * NN + n] == r);
        sCnt[tid] = c;
    }
    for (int i = tid; i < 2 * 16 * 129; i += 256) ((float*)shCS)[i] = 0.0f;
    __syncthreads();
    if (tid == 0) {
        int a = 0;
        for (int i = 0; i < 16; i++) { sStart[i] = a; a += sCnt[i]; }
        sStart[16] = a;
    }
    __syncthreads();
    if (tid < 16) {
        int pos = sStart[tid];
        for (int n = 0; n < 32; n++) {
            if (relation_ids[(b0 + tid) * NN + n] == r) {
                int v = virtual_mask[(b0 + tid) * NN + n] ? 1 : 0;
                sList[pos++] = n | (v << 6) | (tid << 8);
            }
        }
    }

    // stage B: W_f[r][g0..g0+127][0..255] -> split bf16, [g][k] stride 264
    {
        __nv_bfloat16* bh = (__nv_bfloat16*)(dsm + BHI);
        __nv_bfloat16* bl = (__nv_bfloat16*)(dsm + BLO);
        for (int i = tid; i < 128 * 128; i += 256) {
            int gg = i >> 7, k = (i & 127) * 2;
            float2 v = *(const float2*)&W_f[(size_t)r * 65536 + (size_t)(g0 + gg) * 256 + k];
            __nv_bfloat16 hx = __float2bfloat16(v.x);
            __nv_bfloat16 hy = __float2bfloat16(v.y);
            *(uint32_t*)&bh[gg * BSTR + k] = pkbf(v.x, v.y);
            *(uint32_t*)&bl[gg * BSTR + k] =
                pkbf(v.x - __bfloat162float(hx), v.y - __bfloat162float(hy));
        }
    }
    __syncthreads();

    const int count = sStart[16];
    const int ntiles = (count + 31) >> 5;
    const uint32_t smb = smem_u32(dsm);
    const float bfv = b_f[r * HH + g0 + (tid & 127)];

    for (int t = 0; t < ntiles; t++) {
        // ---- stage A tile: 32 children x 256 k, split bf16 ----
        {
            int s = tid >> 3, seg = tid & 7;
            int gs = t * 32 + s;
            const float* src = nullptr;
            if (gs < count) {
                int e = sList[gs];
                src = &child_h[((size_t)(b0 + (e >> 8)) * NN + (e & 63)) * HH + seg * 32];
            }
            __nv_bfloat16* ah = (__nv_bfloat16*)(dsm + AHI);
            __nv_bfloat16* al = (__nv_bfloat16*)(dsm + ALO);
            #pragma unroll
            for (int j = 0; j < 8; j++) {
                float4 v = src ? *(const float4*)(src + j * 4) : make_float4(0.f, 0.f, 0.f, 0.f);
                int col = seg * 32 + j * 4;
                __nv_bfloat16 hx = __float2bfloat16(v.x);
                __nv_bfloat16 hy = __float2bfloat16(v.y);
                __nv_bfloat16 hz = __float2bfloat16(v.z);
                __nv_bfloat16 hw = __float2bfloat16(v.w);
                *(uint32_t*)&ah[s * BSTR + col]     = pkbf(v.x, v.y);
                *(uint32_t*)&ah[s * BSTR + col + 2] = pkbf(v.z, v.w);
                *(uint32_t*)&al[s * BSTR + col] =
                    pkbf(v.x - __bfloat162float(hx), v.y - __bfloat162float(hy));
                *(uint32_t*)&al[s * BSTR + col + 2] =
                    pkbf(v.z - __bfloat162float(hz), v.w - __bfloat162float(hw));
            }
        }
        __syncthreads();

        // ---- mma: each warp computes [32 m][16 n] slice ----
        float d[2][2][4];
        #pragma unroll
        for (int mt = 0; mt < 2; mt++)
            #pragma unroll
            for (int nt = 0; nt < 2; nt++)
                #pragma unroll
                for (int q = 0; q < 4; q++) d[mt][nt][q] = 0.0f;

        const int tIdx = lane >> 3, rsub = lane & 7;
        #pragma unroll
        for (int term = 0; term < 3; term++) {
            uint32_t abase = smb + ((term == 2) ? ALO : AHI);
            uint32_t bbase = smb + ((term == 1) ? BLO : BHI);
            #pragma unroll 4
            for (int kt = 0; kt < 16; kt++) {
                int k0 = kt * 16;
                uint32_t areg[2][4], breg[4];
                #pragma unroll
                for (int mt = 0; mt < 2; mt++) {
                    int row = mt * 16 + ((tIdx & 1) ? 8 : 0) + rsub;
                    int col = k0 + ((tIdx & 2) ? 8 : 0);
                    ldsm4(areg[mt], abase + (uint32_t)(row * BSTR + col) * 2u);
                }
                {
                    // B stored [n][k], k contiguous -> NON-trans ldmatrix:
                    // m0:(n0-7,k0-7)->b0  m1:(n0-7,k8-15)->b1  m2/m3: n+8 tile
                    int n = warp * 16 + ((tIdx & 2) ? 8 : 0) + rsub;
                    int k = k0 + ((tIdx & 1) ? 8 : 0);
                    ldsm4(breg, bbase + (uint32_t)(n * BSTR + k) * 2u);
                }
                #pragma unroll
                for (int mt = 0; mt < 2; mt++)
                    #pragma unroll
                    for (int nt = 0; nt < 2; nt++)
                        mma16816(d[mt][nt], areg[mt], &breg[nt * 2]);
            }
        }

        // ---- write F tile ----
        {
            float* F = (float*)(dsm + FSM);
            int arow = lane >> 2, acol = (lane & 3) * 2;
            #pragma unroll
            for (int mt = 0; mt < 2; mt++)
                #pragma unroll
                for (int nt = 0; nt < 2; nt++) {
                    int col = warp * 16 + nt * 8 + acol;
                    F[(mt * 16 + arow) * FSTR + col]         = d[mt][nt][0];
                    F[(mt * 16 + arow) * FSTR + col + 1]     = d[mt][nt][1];
                    F[(mt * 16 + arow + 8) * FSTR + col]     = d[mt][nt][2];
                    F[(mt * 16 + arow + 8) * FSTR + col + 1] = d[mt][nt][3];
                }
        }
        __syncthreads();

        // ---- fold into per-batch partial csum ----
        {
            const float* F = (const float*)(dsm + FSM);
            int g = tid & 127, hf = tid >> 7;
            int s0 = t * 32 + hf * 16;
            int s1 = min(s0 + 16, count);
            for (int s = s0; s < s1; s++) {
                int e = sList[s];
                int n = e & 63, bl = e >> 8;
                float dcy = ((e >> 6) & 1) ? VDECAY : 1.0f;
                float Fv = F[(s - t * 32) * FSTR + g];
                float cc = child_c[((size_t)(b0 + bl) * NN + n) * HH + g0 + g];
                shCS[hf][bl][g] += (Fv * dcy + bfv) * (cc * dcy);
            }
        }
        __syncthreads();
    }

    for (int i = tid; i < 16 * 128; i += 256) {
        int bl = i >> 7, g = i & 127;
        g_csum3[((size_t)r * BB + b0 + bl) * HH + g0 + g] = shCS[0][bl][g] + shCS[1][bl][g];
    }
}

// ---------------- gates: scalar FFMA + cp.async weights ----------------
#define G_SMEM 81920
__global__ __launch_bounds__(256) void gates_kernel(
    const float* __restrict__ b_i, const float* __restrict__ b_o,
    const float* __restrict__ b_u, float* __restrict__ out)
{
    extern __shared__ char gsm[];
    float* sh_comb = (float*)gsm;             // [16][512]
    float* sh_w    = (float*)(gsm + 32768);   // [2][3*2048]

    const int b0 = blockIdx.x * 16, tid = threadIdx.x, g = tid;

    for (int idx = tid; idx < 16 * 512; idx += 256)
        sh_comb[idx] = g_comb[(size_t)b0 * 512 + idx];

    auto stage = [&](int c, int buf) {
        float* dst = sh_w + buf * 6144;
        for (int i = tid; i < 1536; i += 256) {
            int j = i * 4;
            int g4 = j & 255, kk = (j >> 8) & 7, gate = j >> 11;
            cpa16(dst + j, &g_WgT[((size_t)gate * 512 + c * 8 + kk) * 256 + g4]);
        }
        CPA_COMMIT();
    };

    float ai[16], ao[16], au[16];
    #pragma unroll
    for (int m = 0; m < 16; m++) { ai[m] = 0.f; ao[m] = 0.f; au[m] = 0.f; }

    stage(0, 0);
    __syncthreads();

    #pragma unroll 1
    for (int c = 0; c < 64; c++) {
        int buf = c & 1;
        if (c < 63) stage(c + 1, buf ^ 1);
        else CPA_COMMIT();
        cpa_wait<1>();
        __syncthreads();
        const float* wb = sh_w + buf * 6144;
        #pragma unroll
        for (int kk2 = 0; kk2 < 4; kk2++) {
            int k = c * 8 + kk2 * 2;
            float wi0 = wb[(kk2 * 2) * 256 + g],        wi1 = wb[(kk2 * 2 + 1) * 256 + g];
            float wo0 = wb[2048 + (kk2 * 2) * 256 + g], wo1 = wb[2048 + (kk2 * 2 + 1) * 256 + g];
            float wu0 = wb[4096 + (kk2 * 2) * 256 + g], wu1 = wb[4096 + (kk2 * 2 + 1) * 256 + g];
            #pragma unroll
            for (int m = 0; m < 16; m++) {
                float2 cm = *(const float2*)&sh_comb[m * 512 + k];
                ai[m] = fmaf(cm.x, wi0, fmaf(cm.y, wi1, ai[m]));
                ao[m] = fmaf(cm.x, wo0, fmaf(cm.y, wo1, ao[m]));
                au[m] = fmaf(cm.x, wu0, fmaf(cm.y, wu1, au[m]));
            }
        }
        __syncthreads();
    }
    cpa_wait<0>();

    const float biv = b_i[g], bov = b_o[g], buv = b_u[g];
    #pragma unroll
    for (int m = 0; m < 16; m++) {
        int b = b0 + m;
        float cs = g_csum3[(size_t)b * HH + g]
                 + g_csum3[(size_t)(BB + b) * HH + g]
                 + g_csum3[(size_t)(2 * BB + b) * HH + g];
        float iv = 1.0f / (1.0f + expf(-(ai[m] + biv)));
        float ov = 1.0f / (1.0f + expf(-(ao[m] + bov)));
        float uv = tanhf(au[m] + buv);
        float cv = fmaf(iv, uv, cs);
        float hv = ov * tanhf(cv);
        out[(size_t)b * HH + g]        = hv;   // h first
        out[(size_t)(BB + b) * HH + g] = cv;   // then c
    }
}

// ---------------- launch ----------------
extern "C" void kernel_launch(void* const* d_in, const int* in_sizes, int n_in,
                              void* d_out, int out_size) {
    const float* input_vec = (const float*)d_in[0];
    const float* child_h   = (const float*)d_in[1];
    const float* child_c   = (const float*)d_in[2];
    const int*   rid       = (const int*)d_in[3];
    const int*   vmask     = (const int*)d_in[4];
    const float* rel_emb   = (const float*)d_in[5];
    const float* W_i = (const float*)d_in[6];
    const float* b_i = (const float*)d_in[7];
    const float* W_f = (const float*)d_in[8];
    const float* b_f = (const float*)d_in[9];
    const float* W_o = (const float*)d_in[10];
    const float* b_o = (const float*)d_in[11];
    const float* W_u = (const float*)d_in[12];
    const float* b_u = (const float*)d_in[13];
    const float* w_att = (const float*)d_in[14];
    const float* b_att = (const float*)d_in[15];
    float* out = (float*)d_out;

    cudaFuncSetAttribute(fgemm_mma,    cudaFuncAttributeMaxDynamicSharedMemorySize, FG_DYN);
    cudaFuncSetAttribute(gates_kernel, cudaFuncAttributeMaxDynamicSharedMemorySize, G_SMEM);

    prep_kernel<<<1536, 256>>>(W_i, W_o, W_u);
    attn_kernel<<<BB, 256>>>(input_vec, child_h, rid, vmask, rel_emb, w_att, b_att);
    dim3 fg(BB / 16, RR, 2);
    fgemm_mma<<<fg, 256, FG_DYN>>>(child_h, child_c, rid, vmask, W_f, b_f);
    gates_kernel<<<BB / 16, 256, G_SMEM>>>(b_i, b_o, b_u, out);
}

// round 10
// speedup vs baseline: 2.0467x; 1.4859x over previous
#include <cuda_runtime.h>
#include <cuda_bf16.h>
#include <cstdint>
#include <math.h>

#define BB 4096
#define NN 32
#define HH 256
#define RR 3
#define VDECAY 0.7f

// ---------------- device scratch ----------------
__device__ float g_WgT[3 * 512 * HH];      // [gate][k][g]
__device__ float g_comb[BB * 512];         // [b][input | child_h_sum]
__device__ float g_csum3[RR * BB * HH];    // per-relation partial csum

// ---------------- helpers ----------------
__device__ __forceinline__ uint32_t smem_u32(const void* p) {
    uint32_t a;
    asm("{ .reg .u64 t; cvta.to.shared.u64 t, %1; cvt.u32.u64 %0, t; }" : "=r"(a) : "l"(p));
    return a;
}
__device__ __forceinline__ void ldsm4(uint32_t* r, uint32_t addr) {
    asm volatile("ldmatrix.sync.aligned.m8n8.x4.shared.b16 {%0,%1,%2,%3}, [%4];"
                 : "=r"(r[0]), "=r"(r[1]), "=r"(r[2]), "=r"(r[3]) : "r"(addr));
}
__device__ __forceinline__ void mma16816(float* d, const uint32_t* a, const uint32_t* b) {
    asm volatile("mma.sync.aligned.m16n8k16.row.col.f32.bf16.bf16.f32 "
                 "{%0,%1,%2,%3},{%4,%5,%6,%7},{%8,%9},{%0,%1,%2,%3};"
                 : "+f"(d[0]), "+f"(d[1]), "+f"(d[2]), "+f"(d[3])
                 : "r"(a[0]), "r"(a[1]), "r"(a[2]), "r"(a[3]), "r"(b[0]), "r"(b[1]));
}
__device__ __forceinline__ uint32_t pkbf(float x, float y) {
    __nv_bfloat162 t = __floats2bfloat162_rn(x, y);
    return *(uint32_t*)&t;
}
__device__ __forceinline__ void cpa16(void* sdst, const void* gsrc) {
    unsigned s = (unsigned)__cvta_generic_to_shared(sdst);
    asm volatile("cp.async.ca.shared.global [%0], [%1], 16;" :: "r"(s), "l"(gsrc) : "memory");
}
#define CPA_COMMIT() asm volatile("cp.async.commit_group;" ::: "memory")
template <int N> __device__ __forceinline__ void cpa_wait() {
    asm volatile("cp.async.wait_group %0;" :: "n"(N) : "memory");
}

// ---------------- prep: gate weight transpose ----------------
__global__ void prep_kernel(const float* __restrict__ Wi,
                            const float* __restrict__ Wo,
                            const float* __restrict__ Wu) {
    int idx = blockIdx.x * blockDim.x + threadIdx.x;
    if (idx < 3 * 512 * HH) {
        int g = idx & 255, t = idx >> 8, k = t & 511, gate = t >> 9;
        const float* W = (gate == 0) ? Wi : ((gate == 1) ? Wo : Wu);
        g_WgT[idx] = W[g * 512 + k];
    }
}

// ---------------- attention + comb (validated) ----------------
#define CHS 260
__global__ __launch_bounds__(256) void attn_kernel(
    const float* __restrict__ input_vec, const float* __restrict__ child_h,
    const int* __restrict__ relation_ids, const int* __restrict__ virtual_mask,
    const float* __restrict__ rel_emb, const float* __restrict__ w_att,
    const float* __restrict__ b_att)
{
    __shared__ float sh_ch[NN * CHS];
    __shared__ int   sh_rid[NN];
    __shared__ float sh_decay[NN], sh_score[NN], sh_attn[NN];
    const int b = blockIdx.x, tid = threadIdx.x, lane = tid & 31, warp = tid >> 5;

    if (tid < NN) {
        sh_rid[tid]   = relation_ids[b * NN + tid];
        sh_decay[tid] = virtual_mask[b * NN + tid] ? VDECAY : 1.0f;
    }
    __syncthreads();
    {
        const float* chb = child_h + (size_t)b * NN * HH;
        for (int idx = tid; idx < NN * HH; idx += 256) {
            int n = idx >> 8, h = idx & 255;
            sh_ch[n * CHS + h] = chb[n * HH + h] * sh_decay[n];
        }
    }
    __syncthreads();
    {
        float batt = b_att[0];
        #pragma unroll
        for (int c = 0; c < 4; c++) {
            int p = warp * 4 + c;
            int r = sh_rid[p];
            float s = 0.0f;
            #pragma unroll
            for (int j = 0; j < 8; j++) {
                int h = j * 32 + lane;
                s = fmaf(rel_emb[r * HH + h] + sh_ch[p * CHS + h], w_att[h], s);
            }
            #pragma unroll
            for (int off = 16; off; off >>= 1) s += __shfl_xor_sync(0xffffffffu, s, off);
            if (lane == 0) sh_score[p] = s + batt;
        }
    }
    __syncthreads();
    if (warp == 0) {
        float v = sh_score[lane], m = v;
        #pragma unroll
        for (int off = 16; off; off >>= 1) m = fmaxf(m, __shfl_xor_sync(0xffffffffu, m, off));
        float e = expf(v - m), s = e;
        #pragma unroll
        for (int off = 16; off; off >>= 1) s += __shfl_xor_sync(0xffffffffu, s, off);
        sh_attn[lane] = e / s;
    }
    __syncthreads();
    const int g = tid;
    float hs = 0.0f;
    #pragma unroll
    for (int p = 0; p < NN; p++) hs = fmaf(sh_attn[p], sh_ch[p * CHS + g], hs);
    g_comb[b * 512 + 256 + g] = hs;
    g_comb[b * 512 + g]       = input_vec[(size_t)b * HH + g];
}

// ---------------- fgemm_mma: split-bf16 mma.sync f-matvec ----------------
// grid (256, 3, 2). block 256 = 8 warps.
// dyn smem: Bhi[128][264]bf16, Blo, Ahi[32][264]bf16, Alo, F[32][130]f32, CC[32][128]f32
#define BHI 0
#define BLO 67584
#define AHI 135168
#define ALO 152064
#define FSM 168960
#define CCS 185600
#define FG_DYN 201984
#define BSTR 264
#define FSTR 130

__global__ __launch_bounds__(256) void fgemm_mma(
    const float* __restrict__ child_h,
    const float* __restrict__ child_c,
    const int*   __restrict__ relation_ids,
    const int*   __restrict__ virtual_mask,
    const float* __restrict__ W_f,
    const float* __restrict__ b_f)
{
    extern __shared__ char dsm[];
    __shared__ int   sList[512], sStart[17], sCnt[16];
    __shared__ float shCS[2][16][129];

    const int tid = threadIdx.x, lane = tid & 31, warp = tid >> 5;
    const int b0 = blockIdx.x * 16, r = blockIdx.y, g0 = blockIdx.z * 128;

    // compaction: counts -> prefix -> ordered fill
    if (tid < 16) {
        int c = 0;
        for (int n = 0; n < 32; n++) c += (relation_ids[(b0 + tid) * NN + n] == r);
        sCnt[tid] = c;
    }
    for (int i = tid; i < 2 * 16 * 129; i += 256) ((float*)shCS)[i] = 0.0f;
    __syncthreads();
    if (tid == 0) {
        int a = 0;
        for (int i = 0; i < 16; i++) { sStart[i] = a; a += sCnt[i]; }
        sStart[16] = a;
    }
    __syncthreads();
    if (tid < 16) {
        int pos = sStart[tid];
        for (int n = 0; n < 32; n++) {
            if (relation_ids[(b0 + tid) * NN + n] == r) {
                int v = virtual_mask[(b0 + tid) * NN + n] ? 1 : 0;
                sList[pos++] = n | (v << 6) | (tid << 8);
            }
        }
    }

    // stage B: W_f[r][g0..g0+127][0..255] -> split bf16, [g][k] stride 264
    {
        __nv_bfloat16* bh = (__nv_bfloat16*)(dsm + BHI);
        __nv_bfloat16* bl = (__nv_bfloat16*)(dsm + BLO);
        for (int i = tid; i < 128 * 128; i += 256) {
            int gg = i >> 7, k = (i & 127) * 2;
            float2 v = *(const float2*)&W_f[(size_t)r * 65536 + (size_t)(g0 + gg) * 256 + k];
            __nv_bfloat16 hx = __float2bfloat16(v.x);
            __nv_bfloat16 hy = __float2bfloat16(v.y);
            *(uint32_t*)&bh[gg * BSTR + k] = pkbf(v.x, v.y);
            *(uint32_t*)&bl[gg * BSTR + k] =
                pkbf(v.x - __bfloat162float(hx), v.y - __bfloat162float(hy));
        }
    }
    __syncthreads();

    const int count = sStart[16];
    const int ntiles = (count + 31) >> 5;
    const uint32_t smb = smem_u32(dsm);
    const float bfv = b_f[r * HH + g0 + (tid & 127)];

    for (int t = 0; t < ntiles; t++) {
        // ---- stage A tile: 32 children x 256 k, split bf16 ----
        {
            int s = tid >> 3, seg = tid & 7;
            int gs = t * 32 + s;
            const float* src = nullptr;
            if (gs < count) {
                int e = sList[gs];
                src = &child_h[((size_t)(b0 + (e >> 8)) * NN + (e & 63)) * HH + seg * 32];
            }
            __nv_bfloat16* ah = (__nv_bfloat16*)(dsm + AHI);
            __nv_bfloat16* al = (__nv_bfloat16*)(dsm + ALO);
            #pragma unroll
            for (int j = 0; j < 8; j++) {
                float4 v = src ? *(const float4*)(src + j * 4) : make_float4(0.f, 0.f, 0.f, 0.f);
                int col = seg * 32 + j * 4;
                __nv_bfloat16 hx = __float2bfloat16(v.x);
                __nv_bfloat16 hy = __float2bfloat16(v.y);
                __nv_bfloat16 hz = __float2bfloat16(v.z);
                __nv_bfloat16 hw = __float2bfloat16(v.w);
                *(uint32_t*)&ah[s * BSTR + col]     = pkbf(v.x, v.y);
                *(uint32_t*)&ah[s * BSTR + col + 2] = pkbf(v.z, v.w);
                *(uint32_t*)&al[s * BSTR + col] =
                    pkbf(v.x - __bfloat162float(hx), v.y - __bfloat162float(hy));
                *(uint32_t*)&al[s * BSTR + col + 2] =
                    pkbf(v.z - __bfloat162float(hz), v.w - __bfloat162float(hw));
            }
        }
        __syncthreads();

        // ---- prefetch child_c tile (32 x 128 g-slice) under the MMA phase ----
        {
            for (int i = tid; i < 32 * 32; i += 256) {
                int s = i >> 5, q = i & 31;
                int gs = t * 32 + s;
                if (gs < count) {
                    int e = sList[gs];
                    const float* src = &child_c[((size_t)(b0 + (e >> 8)) * NN + (e & 63)) * HH
                                                + g0 + q * 4];
                    cpa16(dsm + CCS + (s * 128 + q * 4) * 4, src);
                }
            }
            CPA_COMMIT();
        }

        // ---- mma: each warp computes [32 m][16 n] slice ----
        float d[2][2][4];
        #pragma unroll
        for (int mt = 0; mt < 2; mt++)
            #pragma unroll
            for (int nt = 0; nt < 2; nt++)
                #pragma unroll
                for (int q = 0; q < 4; q++) d[mt][nt][q] = 0.0f;

        const int tIdx = lane >> 3, rsub = lane & 7;
        #pragma unroll
        for (int term = 0; term < 3; term++) {
            uint32_t abase = smb + ((term == 2) ? ALO : AHI);
            uint32_t bbase = smb + ((term == 1) ? BLO : BHI);
            #pragma unroll 4
            for (int kt = 0; kt < 16; kt++) {
                int k0 = kt * 16;
                uint32_t areg[2][4], breg[4];
                #pragma unroll
                for (int mt = 0; mt < 2; mt++) {
                    int row = mt * 16 + ((tIdx & 1) ? 8 : 0) + rsub;
                    int col = k0 + ((tIdx & 2) ? 8 : 0);
                    ldsm4(areg[mt], abase + (uint32_t)(row * BSTR + col) * 2u);
                }
                {
                    // B stored [n][k], k contiguous -> NON-trans ldmatrix
                    int n = warp * 16 + ((tIdx & 2) ? 8 : 0) + rsub;
                    int k = k0 + ((tIdx & 1) ? 8 : 0);
                    ldsm4(breg, bbase + (uint32_t)(n * BSTR + k) * 2u);
                }
                #pragma unroll
                for (int mt = 0; mt < 2; mt++)
                    #pragma unroll
                    for (int nt = 0; nt < 2; nt++)
                        mma16816(d[mt][nt], areg[mt], &breg[nt * 2]);
            }
        }

        // ---- write F tile ----
        {
            float* F = (float*)(dsm + FSM);
            int arow = lane >> 2, acol = (lane & 3) * 2;
            #pragma unroll
            for (int mt = 0; mt < 2; mt++)
                #pragma unroll
                for (int nt = 0; nt < 2; nt++) {
                    int col = warp * 16 + nt * 8 + acol;
                    F[(mt * 16 + arow) * FSTR + col]         = d[mt][nt][0];
                    F[(mt * 16 + arow) * FSTR + col + 1]     = d[mt][nt][1];
                    F[(mt * 16 + arow + 8) * FSTR + col]     = d[mt][nt][2];
                    F[(mt * 16 + arow + 8) * FSTR + col + 1] = d[mt][nt][3];
                }
        }
        cpa_wait<0>();
        __syncthreads();

        // ---- fold into per-batch partial csum (child_c now in smem) ----
        {
            const float* F  = (const float*)(dsm + FSM);
            const float* CC = (const float*)(dsm + CCS);
            int g = tid & 127, hf = tid >> 7;
            int s0 = t * 32 + hf * 16;
            int s1 = min(s0 + 16, count);
            for (int s = s0; s < s1; s++) {
                int e = sList[s];
                int bl = e >> 8;
                float dcy = ((e >> 6) & 1) ? VDECAY : 1.0f;
                float Fv = F[(s - t * 32) * FSTR + g];
                float cc = CC[(s - t * 32) * 128 + g];
                shCS[hf][bl][g] += (Fv * dcy + bfv) * (cc * dcy);
            }
        }
        __syncthreads();
    }

    for (int i = tid; i < 16 * 128; i += 256) {
        int bl = i >> 7, g = i & 127;
        g_csum3[((size_t)r * BB + b0 + bl) * HH + g0 + g] = shCS[0][bl][g] + shCS[1][bl][g];
    }
}

// ---------------- gates: scalar FFMA + cp.async weights (8 batches/block) ----
#define G_SMEM 65536
__global__ __launch_bounds__(256) void gates_kernel(
    const float* __restrict__ b_i, const float* __restrict__ b_o,
    const float* __restrict__ b_u, float* __restrict__ out)
{
    extern __shared__ char gsm[];
    float* sh_comb = (float*)gsm;             // [8][512]
    float* sh_w    = (float*)(gsm + 16384);   // [2][3*2048]

    const int b0 = blockIdx.x * 8, tid = threadIdx.x, g = tid;

    for (int idx = tid; idx < 8 * 512; idx += 256)
        sh_comb[idx] = g_comb[(size_t)b0 * 512 + idx];

    auto stage = [&](int c, int buf) {
        float* dst = sh_w + buf * 6144;
        for (int i = tid; i < 1536; i += 256) {
            int j = i * 4;
            int g4 = j & 255, kk = (j >> 8) & 7, gate = j >> 11;
            cpa16(dst + j, &g_WgT[((size_t)gate * 512 + c * 8 + kk) * 256 + g4]);
        }
        CPA_COMMIT();
    };

    float ai[8], ao[8], au[8];
    #pragma unroll
    for (int m = 0; m < 8; m++) { ai[m] = 0.f; ao[m] = 0.f; au[m] = 0.f; }

    stage(0, 0);
    __syncthreads();

    #pragma unroll 1
    for (int c = 0; c < 64; c++) {
        int buf = c & 1;
        if (c < 63) stage(c + 1, buf ^ 1);
        else CPA_COMMIT();
        cpa_wait<1>();
        __syncthreads();
        const float* wb = sh_w + buf * 6144;
        #pragma unroll
        for (int kk2 = 0; kk2 < 4; kk2++) {
            int k = c * 8 + kk2 * 2;
            float wi0 = wb[(kk2 * 2) * 256 + g],        wi1 = wb[(kk2 * 2 + 1) * 256 + g];
            float wo0 = wb[2048 + (kk2 * 2) * 256 + g], wo1 = wb[2048 + (kk2 * 2 + 1) * 256 + g];
            float wu0 = wb[4096 + (kk2 * 2) * 256 + g], wu1 = wb[4096 + (kk2 * 2 + 1) * 256 + g];
            #pragma unroll
            for (int m = 0; m < 8; m++) {
                float2 cm = *(const float2*)&sh_comb[m * 512 + k];
                ai[m] = fmaf(cm.x, wi0, fmaf(cm.y, wi1, ai[m]));
                ao[m] = fmaf(cm.x, wo0, fmaf(cm.y, wo1, ao[m]));
                au[m] = fmaf(cm.x, wu0, fmaf(cm.y, wu1, au[m]));
            }
        }
        __syncthreads();
    }
    cpa_wait<0>();

    const float biv = b_i[g], bov = b_o[g], buv = b_u[g];
    #pragma unroll
    for (int m = 0; m < 8; m++) {
        int b = b0 + m;
        float cs = g_csum3[(size_t)b * HH + g]
                 + g_csum3[(size_t)(BB + b) * HH + g]
                 + g_csum3[(size_t)(2 * BB + b) * HH + g];
        float iv = 1.0f / (1.0f + expf(-(ai[m] + biv)));
        float ov = 1.0f / (1.0f + expf(-(ao[m] + bov)));
        float uv = tanhf(au[m] + buv);
        float cv = fmaf(iv, uv, cs);
        float hv = ov * tanhf(cv);
        out[(size_t)b * HH + g]        = hv;   // h first
        out[(size_t)(BB + b) * HH + g] = cv;   // then c
    }
}

// ---------------- launch ----------------
extern "C" void kernel_launch(void* const* d_in, const int* in_sizes, int n_in,
                              void* d_out, int out_size) {
    const float* input_vec = (const float*)d_in[0];
    const float* child_h   = (const float*)d_in[1];
    const float* child_c   = (const float*)d_in[2];
    const int*   rid       = (const int*)d_in[3];
    const int*   vmask     = (const int*)d_in[4];
    const float* rel_emb   = (const float*)d_in[5];
    const float* W_i = (const float*)d_in[6];
    const float* b_i = (const float*)d_in[7];
    const float* W_f = (const float*)d_in[8];
    const float* b_f = (const float*)d_in[9];
    const float* W_o = (const float*)d_in[10];
    const float* b_o = (const float*)d_in[11];
    const float* W_u = (const float*)d_in[12];
    const float* b_u = (const float*)d_in[13];
    const float* w_att = (const float*)d_in[14];
    const float* b_att = (const float*)d_in[15];
    float* out = (float*)d_out;

    cudaFuncSetAttribute(fgemm_mma,    cudaFuncAttributeMaxDynamicSharedMemorySize, FG_DYN);
    cudaFuncSetAttribute(gates_kernel, cudaFuncAttributeMaxDynamicSharedMemorySize, G_SMEM);

    prep_kernel<<<1536, 256>>>(W_i, W_o, W_u);
    attn_kernel<<<BB, 256>>>(input_vec, child_h, rid, vmask, rel_emb, w_att, b_att);
    dim3 fg(BB / 16, RR, 2);
    fgemm_mma<<<fg, 256, FG_DYN>>>(child_h, child_c, rid, vmask, W_f, b_f);
    gates_kernel<<<BB / 8, 256, G_SMEM>>>(b_i, b_o, b_u, out);
}

// round 11
// speedup vs baseline: 2.5728x; 1.2570x over previous
#include <cuda_runtime.h>
#include <cuda_bf16.h>
#include <cstdint>
#include <math.h>

#define BB 4096
#define NN 32
#define HH 256
#define RR 3
#define VDECAY 0.7f

// ---------------- device scratch ----------------
__device__ float g_WgT[3 * 512 * HH];      // [gate][k][g]
__device__ float g_comb[BB * 512];         // [b][input | child_h_sum]
__device__ float g_csum6[6 * BB * HH];     // [r*2+khalf][b][g] partial csum

// ---------------- helpers ----------------
__device__ __forceinline__ uint32_t smem_u32(const void* p) {
    uint32_t a;
    asm("{ .reg .u64 t; cvta.to.shared.u64 t, %1; cvt.u32.u64 %0, t; }" : "=r"(a) : "l"(p));
    return a;
}
__device__ __forceinline__ void ldsm4(uint32_t* r, uint32_t addr) {
    asm volatile("ldmatrix.sync.aligned.m8n8.x4.shared.b16 {%0,%1,%2,%3}, [%4];"
                 : "=r"(r[0]), "=r"(r[1]), "=r"(r[2]), "=r"(r[3]) : "r"(addr));
}
__device__ __forceinline__ void mma16816(float* d, const uint32_t* a, const uint32_t* b) {
    asm volatile("mma.sync.aligned.m16n8k16.row.col.f32.bf16.bf16.f32 "
                 "{%0,%1,%2,%3},{%4,%5,%6,%7},{%8,%9},{%0,%1,%2,%3};"
                 : "+f"(d[0]), "+f"(d[1]), "+f"(d[2]), "+f"(d[3])
                 : "r"(a[0]), "r"(a[1]), "r"(a[2]), "r"(a[3]), "r"(b[0]), "r"(b[1]));
}
__device__ __forceinline__ uint32_t pkbf(float x, float y) {
    __nv_bfloat162 t = __floats2bfloat162_rn(x, y);
    return *(uint32_t*)&t;
}
__device__ __forceinline__ void cpa16(void* sdst, const void* gsrc) {
    unsigned s = (unsigned)__cvta_generic_to_shared(sdst);
    asm volatile("cp.async.ca.shared.global [%0], [%1], 16;" :: "r"(s), "l"(gsrc) : "memory");
}
#define CPA_COMMIT() asm volatile("cp.async.commit_group;" ::: "memory")
template <int N> __device__ __forceinline__ void cpa_wait() {
    asm volatile("cp.async.wait_group %0;" :: "n"(N) : "memory");
}

// ---------------- prep: gate weight transpose ----------------
__global__ void prep_kernel(const float* __restrict__ Wi,
                            const float* __restrict__ Wo,
                            const float* __restrict__ Wu) {
    int idx = blockIdx.x * blockDim.x + threadIdx.x;
    if (idx < 3 * 512 * HH) {
        int g = idx & 255, t = idx >> 8, k = t & 511, gate = t >> 9;
        const float* W = (gate == 0) ? Wi : ((gate == 1) ? Wo : Wu);
        g_WgT[idx] = W[g * 512 + k];
    }
}

// ---------------- attention + comb (validated) ----------------
#define CHS 260
__global__ __launch_bounds__(256) void attn_kernel(
    const float* __restrict__ input_vec, const float* __restrict__ child_h,
    const int* __restrict__ relation_ids, const int* __restrict__ virtual_mask,
    const float* __restrict__ rel_emb, const float* __restrict__ w_att,
    const float* __restrict__ b_att)
{
    __shared__ float sh_ch[NN * CHS];
    __shared__ int   sh_rid[NN];
    __shared__ float sh_decay[NN], sh_score[NN], sh_attn[NN];
    const int b = blockIdx.x, tid = threadIdx.x, lane = tid & 31, warp = tid >> 5;

    if (tid < NN) {
        sh_rid[tid]   = relation_ids[b * NN + tid];
        sh_decay[tid] = virtual_mask[b * NN + tid] ? VDECAY : 1.0f;
    }
    __syncthreads();
    {
        const float* chb = child_h + (size_t)b * NN * HH;
        for (int idx = tid; idx < NN * HH; idx += 256) {
            int n = idx >> 8, h = idx & 255;
            sh_ch[n * CHS + h] = chb[n * HH + h] * sh_decay[n];
        }
    }
    __syncthreads();
    {
        float batt = b_att[0];
        #pragma unroll
        for (int c = 0; c < 4; c++) {
            int p = warp * 4 + c;
            int r = sh_rid[p];
            float s = 0.0f;
            #pragma unroll
            for (int j = 0; j < 8; j++) {
                int h = j * 32 + lane;
                s = fmaf(rel_emb[r * HH + h] + sh_ch[p * CHS + h], w_att[h], s);
            }
            #pragma unroll
            for (int off = 16; off; off >>= 1) s += __shfl_xor_sync(0xffffffffu, s, off);
            if (lane == 0) sh_score[p] = s + batt;
        }
    }
    __syncthreads();
    if (warp == 0) {
        float v = sh_score[lane], m = v;
        #pragma unroll
        for (int off = 16; off; off >>= 1) m = fmaxf(m, __shfl_xor_sync(0xffffffffu, m, off));
        float e = expf(v - m), s = e;
        #pragma unroll
        for (int off = 16; off; off >>= 1) s += __shfl_xor_sync(0xffffffffu, s, off);
        sh_attn[lane] = e / s;
    }
    __syncthreads();
    const int g = tid;
    float hs = 0.0f;
    #pragma unroll
    for (int p = 0; p < NN; p++) hs = fmaf(sh_attn[p], sh_ch[p * CHS + g], hs);
    g_comb[b * 512 + 256 + g] = hs;
    g_comb[b * 512 + g]       = input_vec[(size_t)b * HH + g];
}

// ---------------- fgemm_mma: k-split split-bf16 mma.sync ----------------
// grid (256, 3, 4): z = khalf*2 + ghalf. block 256 = 8 warps, 2 CTAs/SM.
// dyn smem: Bhi[128][136]bf16, Blo, A(hi+lo)[32][136]bf16 (F overlays A)
#define BSTR 136
#define BHI  0
#define BLO  (128 * BSTR * 2)            // 34816
#define ASM  (2 * 128 * BSTR * 2)        // 69632
#define ALO_OFF (32 * BSTR * 2)          // 8704 within A block
#define FSTR 132
#define FG_DYN (ASM + 2 * 32 * BSTR * 2) // 87040

__global__ __launch_bounds__(256, 2) void fgemm_mma(
    const float* __restrict__ child_h,
    const float* __restrict__ child_c,
    const int*   __restrict__ relation_ids,
    const int*   __restrict__ virtual_mask,
    const float* __restrict__ W_f,
    const float* __restrict__ b_f)
{
    extern __shared__ char dsm[];
    __shared__ int   sList[512], sStart[17], sCnt[16];
    __shared__ float shCS[2][16][129];

    const int tid = threadIdx.x, lane = tid & 31, warp = tid >> 5;
    const int b0 = blockIdx.x * 16, r = blockIdx.y;
    const int ghalf = blockIdx.z & 1, khalf = blockIdx.z >> 1;
    const int g0 = ghalf * 128, k0 = khalf * 128;

    // compaction: counts -> prefix -> ordered fill
    if (tid < 16) {
        int c = 0;
        for (int n = 0; n < 32; n++) c += (relation_ids[(b0 + tid) * NN + n] == r);
        sCnt[tid] = c;
    }
    for (int i = tid; i < 2 * 16 * 129; i += 256) ((float*)shCS)[i] = 0.0f;
    __syncthreads();
    if (tid == 0) {
        int a = 0;
        for (int i = 0; i < 16; i++) { sStart[i] = a; a += sCnt[i]; }
        sStart[16] = a;
    }
    __syncthreads();
    if (tid < 16) {
        int pos = sStart[tid];
        for (int n = 0; n < 32; n++) {
            if (relation_ids[(b0 + tid) * NN + n] == r) {
                int v = virtual_mask[(b0 + tid) * NN + n] ? 1 : 0;
                sList[pos++] = n | (v << 6) | (tid << 8);
            }
        }
    }

    // stage B: W_f[r][g0..g0+127][k0..k0+127] -> split bf16, [g][k] stride 136
    {
        __nv_bfloat16* bh = (__nv_bfloat16*)(dsm + BHI);
        __nv_bfloat16* bl = (__nv_bfloat16*)(dsm + BLO);
        for (int i = tid; i < 128 * 64; i += 256) {
            int gg = i >> 6, k = (i & 63) * 2;
            float2 v = *(const float2*)&W_f[(size_t)r * 65536 + (size_t)(g0 + gg) * 256 + k0 + k];
            __nv_bfloat16 hx = __float2bfloat16(v.x);
            __nv_bfloat16 hy = __float2bfloat16(v.y);
            *(uint32_t*)&bh[gg * BSTR + k] = pkbf(v.x, v.y);
            *(uint32_t*)&bl[gg * BSTR + k] =
                pkbf(v.x - __bfloat162float(hx), v.y - __bfloat162float(hy));
        }
    }
    __syncthreads();

    const int count = sStart[16];
    const int ntiles = (count + 31) >> 5;
    const uint32_t smb = smem_u32(dsm);
    const int gcol = tid & 127, hf = tid >> 7;
    const float bfk = (khalf == 0) ? b_f[r * HH + g0 + gcol] : 0.0f;

    for (int t = 0; t < ntiles; t++) {
        // ---- stage A tile: 32 children x 128 k, split bf16 (overwrites prev F) ----
        {
            int s = tid >> 3, seg = tid & 7;
            int gs = t * 32 + s;
            const float* src = nullptr;
            if (gs < count) {
                int e = sList[gs];
                src = &child_h[((size_t)(b0 + (e >> 8)) * NN + (e & 63)) * HH + k0 + seg * 16];
            }
            __nv_bfloat16* ah = (__nv_bfloat16*)(dsm + ASM);
            __nv_bfloat16* al = (__nv_bfloat16*)(dsm + ASM + ALO_OFF);
            #pragma unroll
            for (int j = 0; j < 4; j++) {
                float4 v = src ? *(const float4*)(src + j * 4) : make_float4(0.f, 0.f, 0.f, 0.f);
                int col = seg * 16 + j * 4;
                __nv_bfloat16 hx = __float2bfloat16(v.x);
                __nv_bfloat16 hy = __float2bfloat16(v.y);
                __nv_bfloat16 hz = __float2bfloat16(v.z);
                __nv_bfloat16 hw = __float2bfloat16(v.w);
                *(uint32_t*)&ah[s * BSTR + col]     = pkbf(v.x, v.y);
                *(uint32_t*)&ah[s * BSTR + col + 2] = pkbf(v.z, v.w);
                *(uint32_t*)&al[s * BSTR + col] =
                    pkbf(v.x - __bfloat162float(hx), v.y - __bfloat162float(hy));
                *(uint32_t*)&al[s * BSTR + col + 2] =
                    pkbf(v.z - __bfloat162float(hz), v.w - __bfloat162float(hw));
            }
        }

        // ---- early-issue child_c loads into registers (consumed in fold) ----
        float ccv[16];
        {
            int sbase = t * 32 + hf * 16;
            #pragma unroll
            for (int j = 0; j < 16; j++) {
                int s = sbase + j;
                float v = 0.0f;
                if (s < count) {
                    int e = sList[s];
                    v = child_c[((size_t)(b0 + (e >> 8)) * NN + (e & 63)) * HH + g0 + gcol];
                }
                ccv[j] = v;
            }
        }
        __syncthreads();

        // ---- mma: each warp computes [32 m][16 n] slice, 8 k-steps ----
        float d[2][2][4];
        #pragma unroll
        for (int mt = 0; mt < 2; mt++)
            #pragma unroll
            for (int nt = 0; nt < 2; nt++)
                #pragma unroll
                for (int q = 0; q < 4; q++) d[mt][nt][q] = 0.0f;

        const int tIdx = lane >> 3, rsub = lane & 7;
        #pragma unroll
        for (int term = 0; term < 3; term++) {
            uint32_t abase = smb + ASM + ((term == 2) ? ALO_OFF : 0);
            uint32_t bbase = smb + ((term == 1) ? BLO : BHI);
            #pragma unroll
            for (int kt = 0; kt < 8; kt++) {
                int kk = kt * 16;
                uint32_t areg[2][4], breg[4];
                #pragma unroll
                for (int mt = 0; mt < 2; mt++) {
                    int row = mt * 16 + ((tIdx & 1) ? 8 : 0) + rsub;
                    int col = kk + ((tIdx & 2) ? 8 : 0);
                    ldsm4(areg[mt], abase + (uint32_t)(row * BSTR + col) * 2u);
                }
                {
                    int n = warp * 16 + ((tIdx & 2) ? 8 : 0) + rsub;
                    int k = kk + ((tIdx & 1) ? 8 : 0);
                    ldsm4(breg, bbase + (uint32_t)(n * BSTR + k) * 2u);
                }
                #pragma unroll
                for (int mt = 0; mt < 2; mt++)
                    #pragma unroll
                    for (int nt = 0; nt < 2; nt++)
                        mma16816(d[mt][nt], areg[mt], &breg[nt * 2]);
            }
        }
        __syncthreads();   // all warps done reading A before F overlays it

        // ---- write F tile into the (now dead) A region ----
        {
            float* F = (float*)(dsm + ASM);
            int arow = lane >> 2, acol = (lane & 3) * 2;
            #pragma unroll
            for (int mt = 0; mt < 2; mt++)
                #pragma unroll
                for (int nt = 0; nt < 2; nt++) {
                    int col = warp * 16 + nt * 8 + acol;
                    F[(mt * 16 + arow) * FSTR + col]         = d[mt][nt][0];
                    F[(mt * 16 + arow) * FSTR + col + 1]     = d[mt][nt][1];
                    F[(mt * 16 + arow + 8) * FSTR + col]     = d[mt][nt][2];
                    F[(mt * 16 + arow + 8) * FSTR + col + 1] = d[mt][nt][3];
                }
        }
        __syncthreads();

        // ---- fold into per-batch partial csum ----
        {
            const float* F = (const float*)(dsm + ASM);
            int sbase = t * 32 + hf * 16;
            int smax = min(16, count - sbase);
            for (int j = 0; j < smax; j++) {
                int e = sList[sbase + j];
                int bl = e >> 8;
                float dcy = ((e >> 6) & 1) ? VDECAY : 1.0f;
                float Fv = F[(hf * 16 + j) * FSTR + gcol];
                shCS[hf][bl][gcol] += (Fv * dcy + bfk) * (ccv[j] * dcy);
            }
        }
        __syncthreads();
    }

    {
        int slot = r * 2 + khalf;
        for (int i = tid; i < 16 * 128; i += 256) {
            int bl = i >> 7, g = i & 127;
            g_csum6[((size_t)slot * BB + b0 + bl) * HH + g0 + g] =
                shCS[0][bl][g] + shCS[1][bl][g];
        }
    }
}

// ---------------- gates: scalar FFMA + cp.async weights (16 batches/block) ----
#define G_SMEM 81920
__global__ __launch_bounds__(256) void gates_kernel(
    const float* __restrict__ b_i, const float* __restrict__ b_o,
    const float* __restrict__ b_u, float* __restrict__ out)
{
    extern __shared__ char gsm[];
    float* sh_comb = (float*)gsm;             // [16][512]
    float* sh_w    = (float*)(gsm + 32768);   // [2][3*2048]

    const int b0 = blockIdx.x * 16, tid = threadIdx.x, g = tid;

    for (int idx = tid; idx < 16 * 512; idx += 256)
        sh_comb[idx] = g_comb[(size_t)b0 * 512 + idx];

    auto stage = [&](int c, int buf) {
        float* dst = sh_w + buf * 6144;
        for (int i = tid; i < 1536; i += 256) {
            int j = i * 4;
            int g4 = j & 255, kk = (j >> 8) & 7, gate = j >> 11;
            cpa16(dst + j, &g_WgT[((size_t)gate * 512 + c * 8 + kk) * 256 + g4]);
        }
        CPA_COMMIT();
    };

    float ai[16], ao[16], au[16];
    #pragma unroll
    for (int m = 0; m < 16; m++) { ai[m] = 0.f; ao[m] = 0.f; au[m] = 0.f; }

    stage(0, 0);
    __syncthreads();

    #pragma unroll 1
    for (int c = 0; c < 64; c++) {
        int buf = c & 1;
        if (c < 63) stage(c + 1, buf ^ 1);
        else CPA_COMMIT();
        cpa_wait<1>();
        __syncthreads();
        const float* wb = sh_w + buf * 6144;
        #pragma unroll
        for (int kk2 = 0; kk2 < 4; kk2++) {
            int k = c * 8 + kk2 * 2;
            float wi0 = wb[(kk2 * 2) * 256 + g],        wi1 = wb[(kk2 * 2 + 1) * 256 + g];
            float wo0 = wb[2048 + (kk2 * 2) * 256 + g], wo1 = wb[2048 + (kk2 * 2 + 1) * 256 + g];
            float wu0 = wb[4096 + (kk2 * 2) * 256 + g], wu1 = wb[4096 + (kk2 * 2 + 1) * 256 + g];
            #pragma unroll
            for (int m = 0; m < 16; m++) {
                float2 cm = *(const float2*)&sh_comb[m * 512 + k];
                ai[m] = fmaf(cm.x, wi0, fmaf(cm.y, wi1, ai[m]));
                ao[m] = fmaf(cm.x, wo0, fmaf(cm.y, wo1, ao[m]));
                au[m] = fmaf(cm.x, wu0, fmaf(cm.y, wu1, au[m]));
            }
        }
        __syncthreads();
    }
    cpa_wait<0>();

    const float biv = b_i[g], bov = b_o[g], buv = b_u[g];
    #pragma unroll
    for (int m = 0; m < 16; m++) {
        int b = b0 + m;
        float cs = 0.0f;
        #pragma unroll
        for (int slot = 0; slot < 6; slot++)
            cs += g_csum6[((size_t)slot * BB + b) * HH + g];
        float iv = 1.0f / (1.0f + expf(-(ai[m] + biv)));
        float ov = 1.0f / (1.0f + expf(-(ao[m] + bov)));
        float uv = tanhf(au[m] + buv);
        float cv = fmaf(iv, uv, cs);
        float hv = ov * tanhf(cv);
        out[(size_t)b * HH + g]        = hv;   // h first
        out[(size_t)(BB + b) * HH + g] = cv;   // then c
    }
}

// ---------------- launch ----------------
extern "C" void kernel_launch(void* const* d_in, const int* in_sizes, int n_in,
                              void* d_out, int out_size) {
    const float* input_vec = (const float*)d_in[0];
    const float* child_h   = (const float*)d_in[1];
    const float* child_c   = (const float*)d_in[2];
    const int*   rid       = (const int*)d_in[3];
    const int*   vmask     = (const int*)d_in[4];
    const float* rel_emb   = (const float*)d_in[5];
    const float* W_i = (const float*)d_in[6];
    const float* b_i = (const float*)d_in[7];
    const float* W_f = (const float*)d_in[8];
    const float* b_f = (const float*)d_in[9];
    const float* W_o = (const float*)d_in[10];
    const float* b_o = (const float*)d_in[11];
    const float* W_u = (const float*)d_in[12];
    const float* b_u = (const float*)d_in[13];
    const float* w_att = (const float*)d_in[14];
    const float* b_att = (const float*)d_in[15];
    float* out = (float*)d_out;

    cudaFuncSetAttribute(fgemm_mma,    cudaFuncAttributeMaxDynamicSharedMemorySize, FG_DYN);
    cudaFuncSetAttribute(gates_kernel, cudaFuncAttributeMaxDynamicSharedMemorySize, G_SMEM);

    prep_kernel<<<1536, 256>>>(W_i, W_o, W_u);
    attn_kernel<<<BB, 256>>>(input_vec, child_h, rid, vmask, rel_emb, w_att, b_att);
    dim3 fg(BB / 16, RR, 4);
    fgemm_mma<<<fg, 256, FG_DYN>>>(child_h, child_c, rid, vmask, W_f, b_f);
    gates_kernel<<<BB / 16, 256, G_SMEM>>>(b_i, b_o, b_u, out);
}

// round 12
// speedup vs baseline: 2.5957x; 1.0089x over previous
#include <cuda_runtime.h>
#include <cuda_bf16.h>
#include <cstdint>
#include <math.h>

#define BB 4096
#define NN 32
#define HH 256
#define RR 3
#define VDECAY 0.7f

// ---------------- device scratch ----------------
__device__ float g_WgT[3 * 512 * HH];      // [gate][k][g]
__device__ float g_comb[BB * 512];         // [b][input | child_h_sum]
__device__ float g_csum6[6 * BB * HH];     // [r*2+khalf][b][g] partial csum

// ---------------- helpers ----------------
__device__ __forceinline__ uint32_t smem_u32(const void* p) {
    uint32_t a;
    asm("{ .reg .u64 t; cvta.to.shared.u64 t, %1; cvt.u32.u64 %0, t; }" : "=r"(a) : "l"(p));
    return a;
}
__device__ __forceinline__ void ldsm4(uint32_t* r, uint32_t addr) {
    asm volatile("ldmatrix.sync.aligned.m8n8.x4.shared.b16 {%0,%1,%2,%3}, [%4];"
                 : "=r"(r[0]), "=r"(r[1]), "=r"(r[2]), "=r"(r[3]) : "r"(addr));
}
__device__ __forceinline__ void mma16816(float* d, const uint32_t* a, const uint32_t* b) {
    asm volatile("mma.sync.aligned.m16n8k16.row.col.f32.bf16.bf16.f32 "
                 "{%0,%1,%2,%3},{%4,%5,%6,%7},{%8,%9},{%0,%1,%2,%3};"
                 : "+f"(d[0]), "+f"(d[1]), "+f"(d[2]), "+f"(d[3])
                 : "r"(a[0]), "r"(a[1]), "r"(a[2]), "r"(a[3]), "r"(b[0]), "r"(b[1]));
}
__device__ __forceinline__ uint32_t pkbf(float x, float y) {
    __nv_bfloat162 t = __floats2bfloat162_rn(x, y);
    return *(uint32_t*)&t;
}
__device__ __forceinline__ void cpa16(void* sdst, const void* gsrc) {
    unsigned s = (unsigned)__cvta_generic_to_shared(sdst);
    asm volatile("cp.async.ca.shared.global [%0], [%1], 16;" :: "r"(s), "l"(gsrc) : "memory");
}
#define CPA_COMMIT() asm volatile("cp.async.commit_group;" ::: "memory")
template <int N> __device__ __forceinline__ void cpa_wait() {
    asm volatile("cp.async.wait_group %0;" :: "n"(N) : "memory");
}

// ---------------- prep: gate weight transpose ----------------
__global__ void prep_kernel(const float* __restrict__ Wi,
                            const float* __restrict__ Wo,
                            const float* __restrict__ Wu) {
    int idx = blockIdx.x * blockDim.x + threadIdx.x;
    if (idx < 3 * 512 * HH) {
        int g = idx & 255, t = idx >> 8, k = t & 511, gate = t >> 9;
        const float* W = (gate == 0) ? Wi : ((gate == 1) ? Wo : Wu);
        g_WgT[idx] = W[g * 512 + k];
    }
}

// ---------------- attention + comb (validated) ----------------
#define CHS 260
__global__ __launch_bounds__(256) void attn_kernel(
    const float* __restrict__ input_vec, const float* __restrict__ child_h,
    const int* __restrict__ relation_ids, const int* __restrict__ virtual_mask,
    const float* __restrict__ rel_emb, const float* __restrict__ w_att,
    const float* __restrict__ b_att)
{
    __shared__ float sh_ch[NN * CHS];
    __shared__ int   sh_rid[NN];
    __shared__ float sh_decay[NN], sh_score[NN], sh_attn[NN];
    const int b = blockIdx.x, tid = threadIdx.x, lane = tid & 31, warp = tid >> 5;

    if (tid < NN) {
        sh_rid[tid]   = relation_ids[b * NN + tid];
        sh_decay[tid] = virtual_mask[b * NN + tid] ? VDECAY : 1.0f;
    }
    __syncthreads();
    {
        const float* chb = child_h + (size_t)b * NN * HH;
        for (int idx = tid; idx < NN * HH; idx += 256) {
            int n = idx >> 8, h = idx & 255;
            sh_ch[n * CHS + h] = chb[n * HH + h] * sh_decay[n];
        }
    }
    __syncthreads();
    {
        float batt = b_att[0];
        #pragma unroll
        for (int c = 0; c < 4; c++) {
            int p = warp * 4 + c;
            int r = sh_rid[p];
            float s = 0.0f;
            #pragma unroll
            for (int j = 0; j < 8; j++) {
                int h = j * 32 + lane;
                s = fmaf(rel_emb[r * HH + h] + sh_ch[p * CHS + h], w_att[h], s);
            }
            #pragma unroll
            for (int off = 16; off; off >>= 1) s += __shfl_xor_sync(0xffffffffu, s, off);
            if (lane == 0) sh_score[p] = s + batt;
        }
    }
    __syncthreads();
    if (warp == 0) {
        float v = sh_score[lane], m = v;
        #pragma unroll
        for (int off = 16; off; off >>= 1) m = fmaxf(m, __shfl_xor_sync(0xffffffffu, m, off));
        float e = expf(v - m), s = e;
        #pragma unroll
        for (int off = 16; off; off >>= 1) s += __shfl_xor_sync(0xffffffffu, s, off);
        sh_attn[lane] = e / s;
    }
    __syncthreads();
    const int g = tid;
    float hs = 0.0f;
    #pragma unroll
    for (int p = 0; p < NN; p++) hs = fmaf(sh_attn[p], sh_ch[p * CHS + g], hs);
    g_comb[b * 512 + 256 + g] = hs;
    g_comb[b * 512 + g]       = input_vec[(size_t)b * HH + g];
}

// ---------------- fgemm_mma: k-split split-bf16, B-hi frags in registers ----
// grid (256, 3, 4): z = khalf*2 + ghalf. block 256 = 8 warps, 2 CTAs/SM.
// dyn smem: Bhi[128][136]bf16, Blo, A(hi+lo)[32][136]bf16 (F overlays A)
#define BSTR 136
#define BHI  0
#define BLO  (128 * BSTR * 2)            // 34816
#define ASM  (2 * 128 * BSTR * 2)        // 69632
#define ALO_OFF (32 * BSTR * 2)          // 8704 within A block
#define FSTR 132
#define FG_DYN (ASM + 2 * 32 * BSTR * 2) // 87040

__global__ __launch_bounds__(256, 2) void fgemm_mma(
    const float* __restrict__ child_h,
    const float* __restrict__ child_c,
    const int*   __restrict__ relation_ids,
    const int*   __restrict__ virtual_mask,
    const float* __restrict__ W_f,
    const float* __restrict__ b_f)
{
    extern __shared__ char dsm[];
    __shared__ int   sList[512], sStart[17], sCnt[16];
    __shared__ float shCS[2][16][129];

    const int tid = threadIdx.x, lane = tid & 31, warp = tid >> 5;
    const int b0 = blockIdx.x * 16, r = blockIdx.y;
    const int ghalf = blockIdx.z & 1, khalf = blockIdx.z >> 1;
    const int g0 = ghalf * 128, k0 = khalf * 128;

    // compaction: counts -> prefix -> ordered fill
    if (tid < 16) {
        int c = 0;
        for (int n = 0; n < 32; n++) c += (relation_ids[(b0 + tid) * NN + n] == r);
        sCnt[tid] = c;
    }
    for (int i = tid; i < 2 * 16 * 129; i += 256) ((float*)shCS)[i] = 0.0f;
    __syncthreads();
    if (tid == 0) {
        int a = 0;
        for (int i = 0; i < 16; i++) { sStart[i] = a; a += sCnt[i]; }
        sStart[16] = a;
    }
    __syncthreads();
    if (tid < 16) {
        int pos = sStart[tid];
        for (int n = 0; n < 32; n++) {
            if (relation_ids[(b0 + tid) * NN + n] == r) {
                int v = virtual_mask[(b0 + tid) * NN + n] ? 1 : 0;
                sList[pos++] = n | (v << 6) | (tid << 8);
            }
        }
    }

    // stage B: W_f[r][g0..g0+127][k0..k0+127] -> split bf16, [g][k] stride 136
    {
        __nv_bfloat16* bh = (__nv_bfloat16*)(dsm + BHI);
        __nv_bfloat16* bl = (__nv_bfloat16*)(dsm + BLO);
        for (int i = tid; i < 128 * 64; i += 256) {
            int gg = i >> 6, k = (i & 63) * 2;
            float2 v = *(const float2*)&W_f[(size_t)r * 65536 + (size_t)(g0 + gg) * 256 + k0 + k];
            __nv_bfloat16 hx = __float2bfloat16(v.x);
            __nv_bfloat16 hy = __float2bfloat16(v.y);
            *(uint32_t*)&bh[gg * BSTR + k] = pkbf(v.x, v.y);
            *(uint32_t*)&bl[gg * BSTR + k] =
                pkbf(v.x - __bfloat162float(hx), v.y - __bfloat162float(hy));
        }
    }
    __syncthreads();

    const int count = sStart[16];
    const int ntiles = (count + 31) >> 5;
    const uint32_t smb = smem_u32(dsm);
    const int gcol = tid & 127, hf = tid >> 7;
    const float bfk = (khalf == 0) ? b_f[r * HH + g0 + gcol] : 0.0f;
    const int tIdx = lane >> 3, rsub = lane & 7;

    // ---- preload B-hi fragments for this warp's 16 n-cols (invariant) ----
    uint32_t bhreg[8][4];
    {
        int n = warp * 16 + ((tIdx & 2) ? 8 : 0) + rsub;
        #pragma unroll
        for (int kt = 0; kt < 8; kt++) {
            int k = kt * 16 + ((tIdx & 1) ? 8 : 0);
            ldsm4(bhreg[kt], smb + BHI + (uint32_t)(n * BSTR + k) * 2u);
        }
    }

    for (int t = 0; t < ntiles; t++) {
        // ---- stage A tile: 32 children x 128 k, split bf16 (overwrites prev F) ----
        {
            int s = tid >> 3, seg = tid & 7;
            int gs = t * 32 + s;
            const float* src = nullptr;
            if (gs < count) {
                int e = sList[gs];
                src = &child_h[((size_t)(b0 + (e >> 8)) * NN + (e & 63)) * HH + k0 + seg * 16];
            }
            __nv_bfloat16* ah = (__nv_bfloat16*)(dsm + ASM);
            __nv_bfloat16* al = (__nv_bfloat16*)(dsm + ASM + ALO_OFF);
            #pragma unroll
            for (int j = 0; j < 4; j++) {
                float4 v = src ? *(const float4*)(src + j * 4) : make_float4(0.f, 0.f, 0.f, 0.f);
                int col = seg * 16 + j * 4;
                __nv_bfloat16 hx = __float2bfloat16(v.x);
                __nv_bfloat16 hy = __float2bfloat16(v.y);
                __nv_bfloat16 hz = __float2bfloat16(v.z);
                __nv_bfloat16 hw = __float2bfloat16(v.w);
                *(uint32_t*)&ah[s * BSTR + col]     = pkbf(v.x, v.y);
                *(uint32_t*)&ah[s * BSTR + col + 2] = pkbf(v.z, v.w);
                *(uint32_t*)&al[s * BSTR + col] =
                    pkbf(v.x - __bfloat162float(hx), v.y - __bfloat162float(hy));
                *(uint32_t*)&al[s * BSTR + col + 2] =
                    pkbf(v.z - __bfloat162float(hz), v.w - __bfloat162float(hw));
            }
        }

        // ---- early-issue child_c loads into registers (consumed in fold) ----
        float ccv[16];
        {
            int sbase = t * 32 + hf * 16;
            #pragma unroll
            for (int j = 0; j < 16; j++) {
                int s = sbase + j;
                float v = 0.0f;
                if (s < count) {
                    int e = sList[s];
                    v = child_c[((size_t)(b0 + (e >> 8)) * NN + (e & 63)) * HH + g0 + gcol];
                }
                ccv[j] = v;
            }
        }
        __syncthreads();

        // ---- mma: pass 1 = Ah·Bh + Ah·Bl, pass 2 = Al·Bh ----
        float d[2][2][4];
        #pragma unroll
        for (int mt = 0; mt < 2; mt++)
            #pragma unroll
            for (int nt = 0; nt < 2; nt++)
                #pragma unroll
                for (int q = 0; q < 4; q++) d[mt][nt][q] = 0.0f;

        {
            const uint32_t ahb = smb + ASM;
            const uint32_t alb = smb + ASM + ALO_OFF;
            const uint32_t blb = smb + BLO;
            int brow = warp * 16 + ((tIdx & 2) ? 8 : 0) + rsub;
            #pragma unroll
            for (int kt = 0; kt < 8; kt++) {
                int kk = kt * 16;
                int kfrag = kk + ((tIdx & 1) ? 8 : 0);
                uint32_t areg[2][4], blreg[4];
                #pragma unroll
                for (int mt = 0; mt < 2; mt++) {
                    int row = mt * 16 + ((tIdx & 1) ? 8 : 0) + rsub;
                    int col = kk + ((tIdx & 2) ? 8 : 0);
                    ldsm4(areg[mt], ahb + (uint32_t)(row * BSTR + col) * 2u);
                }
                ldsm4(blreg, blb + (uint32_t)(brow * BSTR + kfrag) * 2u);
                #pragma unroll
                for (int mt = 0; mt < 2; mt++)
                    #pragma unroll
                    for (int nt = 0; nt < 2; nt++) {
                        mma16816(d[mt][nt], areg[mt], &bhreg[kt][nt * 2]);
                        mma16816(d[mt][nt], areg[mt], &blreg[nt * 2]);
                    }
            }
            #pragma unroll
            for (int kt = 0; kt < 8; kt++) {
                int kk = kt * 16;
                uint32_t areg[2][4];
                #pragma unroll
                for (int mt = 0; mt < 2; mt++) {
                    int row = mt * 16 + ((tIdx & 1) ? 8 : 0) + rsub;
                    int col = kk + ((tIdx & 2) ? 8 : 0);
                    ldsm4(areg[mt], alb + (uint32_t)(row * BSTR + col) * 2u);
                }
                #pragma unroll
                for (int mt = 0; mt < 2; mt++)
                    #pragma unroll
                    for (int nt = 0; nt < 2; nt++)
                        mma16816(d[mt][nt], areg[mt], &bhreg[kt][nt * 2]);
            }
        }
        __syncthreads();   // all warps done reading A before F overlays it

        // ---- write F tile into the (now dead) A region ----
        {
            float* F = (float*)(dsm + ASM);
            int arow = lane >> 2, acol = (lane & 3) * 2;
            #pragma unroll
            for (int mt = 0; mt < 2; mt++)
                #pragma unroll
                for (int nt = 0; nt < 2; nt++) {
                    int col = warp * 16 + nt * 8 + acol;
                    F[(mt * 16 + arow) * FSTR + col]         = d[mt][nt][0];
                    F[(mt * 16 + arow) * FSTR + col + 1]     = d[mt][nt][1];
                    F[(mt * 16 + arow + 8) * FSTR + col]     = d[mt][nt][2];
                    F[(mt * 16 + arow + 8) * FSTR + col + 1] = d[mt][nt][3];
                }
        }
        __syncthreads();

        // ---- fold into per-batch partial csum ----
        {
            const float* F = (const float*)(dsm + ASM);
            int sbase = t * 32 + hf * 16;
            int smax = min(16, count - sbase);
            for (int j = 0; j < smax; j++) {
                int e = sList[sbase + j];
                int bl = e >> 8;
                float dcy = ((e >> 6) & 1) ? VDECAY : 1.0f;
                float Fv = F[(hf * 16 + j) * FSTR + gcol];
                shCS[hf][bl][gcol] += (Fv * dcy + bfk) * (ccv[j] * dcy);
            }
        }
        __syncthreads();
    }

    {
        int slot = r * 2 + khalf;
        for (int i = tid; i < 16 * 128; i += 256) {
            int bl = i >> 7, g = i & 127;
            g_csum6[((size_t)slot * BB + b0 + bl) * HH + g0 + g] =
                shCS[0][bl][g] + shCS[1][bl][g];
        }
    }
}

// ---------------- gates: scalar FFMA + cp.async weights (16 batches/block) ----
#define G_SMEM 81920
__global__ __launch_bounds__(256) void gates_kernel(
    const float* __restrict__ b_i, const float* __restrict__ b_o,
    const float* __restrict__ b_u, float* __restrict__ out)
{
    extern __shared__ char gsm[];
    float* sh_comb = (float*)gsm;             // [16][512]
    float* sh_w    = (float*)(gsm + 32768);   // [2][3*2048]

    const int b0 = blockIdx.x * 16, tid = threadIdx.x, g = tid;

    for (int idx = tid; idx < 16 * 512; idx += 256)
        sh_comb[idx] = g_comb[(size_t)b0 * 512 + idx];

    auto stage = [&](int c, int buf) {
        float* dst = sh_w + buf * 6144;
        for (int i = tid; i < 1536; i += 256) {
            int j = i * 4;
            int g4 = j & 255, kk = (j >> 8) & 7, gate = j >> 11;
            cpa16(dst + j, &g_WgT[((size_t)gate * 512 + c * 8 + kk) * 256 + g4]);
        }
        CPA_COMMIT();
    };

    float ai[16], ao[16], au[16];
    #pragma unroll
    for (int m = 0; m < 16; m++) { ai[m] = 0.f; ao[m] = 0.f; au[m] = 0.f; }

    stage(0, 0);
    __syncthreads();

    #pragma unroll 1
    for (int c = 0; c < 64; c++) {
        int buf = c & 1;
        if (c < 63) stage(c + 1, buf ^ 1);
        else CPA_COMMIT();
        cpa_wait<1>();
        __syncthreads();
        const float* wb = sh_w + buf * 6144;
        #pragma unroll
        for (int kk2 = 0; kk2 < 4; kk2++) {
            int k = c * 8 + kk2 * 2;
            float wi0 = wb[(kk2 * 2) * 256 + g],        wi1 = wb[(kk2 * 2 + 1) * 256 + g];
            float wo0 = wb[2048 + (kk2 * 2) * 256 + g], wo1 = wb[2048 + (kk2 * 2 + 1) * 256 + g];
            float wu0 = wb[4096 + (kk2 * 2) * 256 + g], wu1 = wb[4096 + (kk2 * 2 + 1) * 256 + g];
            #pragma unroll
            for (int m = 0; m < 16; m++) {
                float2 cm = *(const float2*)&sh_comb[m * 512 + k];
                ai[m] = fmaf(cm.x, wi0, fmaf(cm.y, wi1, ai[m]));
                ao[m] = fmaf(cm.x, wo0, fmaf(cm.y, wo1, ao[m]));
                au[m] = fmaf(cm.x, wu0, fmaf(cm.y, wu1, au[m]));
            }
        }
        __syncthreads();
    }
    cpa_wait<0>();

    const float biv = b_i[g], bov = b_o[g], buv = b_u[g];
    #pragma unroll
    for (int m = 0; m < 16; m++) {
        int b = b0 + m;
        float cs = 0.0f;
        #pragma unroll
        for (int slot = 0; slot < 6; slot++)
            cs += g_csum6[((size_t)slot * BB + b) * HH + g];
        float iv = 1.0f / (1.0f + expf(-(ai[m] + biv)));
        float ov = 1.0f / (1.0f + expf(-(ao[m] + bov)));
        float uv = tanhf(au[m] + buv);
        float cv = fmaf(iv, uv, cs);
        float hv = ov * tanhf(cv);
        out[(size_t)b * HH + g]        = hv;   // h first
        out[(size_t)(BB + b) * HH + g] = cv;   // then c
    }
}

// ---------------- launch ----------------
extern "C" void kernel_launch(void* const* d_in, const int* in_sizes, int n_in,
                              void* d_out, int out_size) {
    const float* input_vec = (const float*)d_in[0];
    const float* child_h   = (const float*)d_in[1];
    const float* child_c   = (const float*)d_in[2];
    const int*   rid       = (const int*)d_in[3];
    const int*   vmask     = (const int*)d_in[4];
    const float* rel_emb   = (const float*)d_in[5];
    const float* W_i = (const float*)d_in[6];
    const float* b_i = (const float*)d_in[7];
    const float* W_f = (const float*)d_in[8];
    const float* b_f = (const float*)d_in[9];
    const float* W_o = (const float*)d_in[10];
    const float* b_o = (const float*)d_in[11];
    const float* W_u = (const float*)d_in[12];
    const float* b_u = (const float*)d_in[13];
    const float* w_att = (const float*)d_in[14];
    const float* b_att = (const float*)d_in[15];
    float* out = (float*)d_out;

    cudaFuncSetAttribute(fgemm_mma,    cudaFuncAttributeMaxDynamicSharedMemorySize, FG_DYN);
    cudaFuncSetAttribute(gates_kernel, cudaFuncAttributeMaxDynamicSharedMemorySize, G_SMEM);

    prep_kernel<<<1536, 256>>>(W_i, W_o, W_u);
    dim3 fg(BB / 16, RR, 4);
    fgemm_mma<<<fg, 256, FG_DYN>>>(child_h, child_c, rid, vmask, W_f, b_f);
    attn_kernel<<<BB, 256>>>(input_vec, child_h, rid, vmask, rel_emb, w_att, b_att);
    gates_kernel<<<BB / 16, 256, G_SMEM>>>(b_i, b_o, b_u, out);
}

// round 13
// speedup vs baseline: 2.8280x; 1.0895x over previous
#include <cuda_runtime.h>
#include <cuda_bf16.h>
#include <cuda_fp16.h>
#include <cstdint>
#include <math.h>

#define BB 4096
#define NN 32
#define HH 256
#define RR 3
#define VDECAY 0.7f

// ---------------- device scratch ----------------
__device__ float g_WgT[3 * 512 * HH];      // [gate][k][g]
__device__ float g_comb[BB * 512];         // [b][input | child_h_sum]
__device__ float g_csum6[6 * BB * HH];     // [r*2+khalf][b][g] partial csum

// ---------------- helpers ----------------
__device__ __forceinline__ uint32_t smem_u32(const void* p) {
    uint32_t a;
    asm("{ .reg .u64 t; cvta.to.shared.u64 t, %1; cvt.u32.u64 %0, t; }" : "=r"(a) : "l"(p));
    return a;
}
__device__ __forceinline__ void ldsm4(uint32_t* r, uint32_t addr) {
    asm volatile("ldmatrix.sync.aligned.m8n8.x4.shared.b16 {%0,%1,%2,%3}, [%4];"
                 : "=r"(r[0]), "=r"(r[1]), "=r"(r[2]), "=r"(r[3]) : "r"(addr));
}
__device__ __forceinline__ void mma16816h(float* d, const uint32_t* a, const uint32_t* b) {
    asm volatile("mma.sync.aligned.m16n8k16.row.col.f32.f16.f16.f32 "
                 "{%0,%1,%2,%3},{%4,%5,%6,%7},{%8,%9},{%0,%1,%2,%3};"
                 : "+f"(d[0]), "+f"(d[1]), "+f"(d[2]), "+f"(d[3])
                 : "r"(a[0]), "r"(a[1]), "r"(a[2]), "r"(a[3]), "r"(b[0]), "r"(b[1]));
}
__device__ __forceinline__ uint32_t pkhf(float x, float y) {
    __half2 t = __floats2half2_rn(x, y);
    return *(uint32_t*)&t;
}
__device__ __forceinline__ void cpa16(void* sdst, const void* gsrc) {
    unsigned s = (unsigned)__cvta_generic_to_shared(sdst);
    asm volatile("cp.async.ca.shared.global [%0], [%1], 16;" :: "r"(s), "l"(gsrc) : "memory");
}
#define CPA_COMMIT() asm volatile("cp.async.commit_group;" ::: "memory")
template <int N> __device__ __forceinline__ void cpa_wait() {
    asm volatile("cp.async.wait_group %0;" :: "n"(N) : "memory");
}

// ---------------- prep: gate weight transpose ----------------
__global__ void prep_kernel(const float* __restrict__ Wi,
                            const float* __restrict__ Wo,
                            const float* __restrict__ Wu) {
    int idx = blockIdx.x * blockDim.x + threadIdx.x;
    if (idx < 3 * 512 * HH) {
        int g = idx & 255, t = idx >> 8, k = t & 511, gate = t >> 9;
        const float* W = (gate == 0) ? Wi : ((gate == 1) ? Wo : Wu);
        g_WgT[idx] = W[g * 512 + k];
    }
}

// ---------------- attention + comb (validated) ----------------
#define CHS 260
__global__ __launch_bounds__(256) void attn_kernel(
    const float* __restrict__ input_vec, const float* __restrict__ child_h,
    const int* __restrict__ relation_ids, const int* __restrict__ virtual_mask,
    const float* __restrict__ rel_emb, const float* __restrict__ w_att,
    const float* __restrict__ b_att)
{
    __shared__ float sh_ch[NN * CHS];
    __shared__ int   sh_rid[NN];
    __shared__ float sh_decay[NN], sh_score[NN], sh_attn[NN];
    const int b = blockIdx.x, tid = threadIdx.x, lane = tid & 31, warp = tid >> 5;

    if (tid < NN) {
        sh_rid[tid]   = relation_ids[b * NN + tid];
        sh_decay[tid] = virtual_mask[b * NN + tid] ? VDECAY : 1.0f;
    }
    __syncthreads();
    {
        const float* chb = child_h + (size_t)b * NN * HH;
        for (int idx = tid; idx < NN * HH; idx += 256) {
            int n = idx >> 8, h = idx & 255;
            sh_ch[n * CHS + h] = chb[n * HH + h] * sh_decay[n];
        }
    }
    __syncthreads();
    {
        float batt = b_att[0];
        #pragma unroll
        for (int c = 0; c < 4; c++) {
            int p = warp * 4 + c;
            int r = sh_rid[p];
            float s = 0.0f;
            #pragma unroll
            for (int j = 0; j < 8; j++) {
                int h = j * 32 + lane;
                s = fmaf(rel_emb[r * HH + h] + sh_ch[p * CHS + h], w_att[h], s);
            }
            #pragma unroll
            for (int off = 16; off; off >>= 1) s += __shfl_xor_sync(0xffffffffu, s, off);
            if (lane == 0) sh_score[p] = s + batt;
        }
    }
    __syncthreads();
    if (warp == 0) {
        float v = sh_score[lane], m = v;
        #pragma unroll
        for (int off = 16; off; off >>= 1) m = fmaxf(m, __shfl_xor_sync(0xffffffffu, m, off));
        float e = expf(v - m), s = e;
        #pragma unroll
        for (int off = 16; off; off >>= 1) s += __shfl_xor_sync(0xffffffffu, s, off);
        sh_attn[lane] = e / s;
    }
    __syncthreads();
    const int g = tid;
    float hs = 0.0f;
    #pragma unroll
    for (int p = 0; p < NN; p++) hs = fmaf(sh_attn[p], sh_ch[p * CHS + g], hs);
    g_comb[b * 512 + 256 + g] = hs;
    g_comb[b * 512 + g]       = input_vec[(size_t)b * HH + g];
}

// ---------------- fgemm_mma: k-split fp16 2-term, B-hi frags in registers ----
// grid (256, 3, 4): z = khalf*2 + ghalf. block 256 = 8 warps, 2 CTAs/SM.
// dyn smem: Bhi[128][136]fp16, Blo, A-hi[32][136]fp16 (F overlays A region)
#define BSTR 136
#define BHI  0
#define BLO  (128 * BSTR * 2)            // 34816
#define ASM  (2 * 128 * BSTR * 2)        // 69632
#define FSTR 132
#define FG_DYN (ASM + 2 * 32 * BSTR * 2) // 87040 (A uses first half; F needs 16.9KB)

__global__ __launch_bounds__(256, 2) void fgemm_mma(
    const float* __restrict__ child_h,
    const float* __restrict__ child_c,
    const int*   __restrict__ relation_ids,
    const int*   __restrict__ virtual_mask,
    const float* __restrict__ W_f,
    const float* __restrict__ b_f)
{
    extern __shared__ char dsm[];
    __shared__ int   sList[512], sStart[17], sCnt[16];
    __shared__ float shCS[2][16][129];

    const int tid = threadIdx.x, lane = tid & 31, warp = tid >> 5;
    const int b0 = blockIdx.x * 16, r = blockIdx.y;
    const int ghalf = blockIdx.z & 1, khalf = blockIdx.z >> 1;
    const int g0 = ghalf * 128, k0 = khalf * 128;

    // compaction: counts -> prefix -> ordered fill
    if (tid < 16) {
        int c = 0;
        for (int n = 0; n < 32; n++) c += (relation_ids[(b0 + tid) * NN + n] == r);
        sCnt[tid] = c;
    }
    for (int i = tid; i < 2 * 16 * 129; i += 256) ((float*)shCS)[i] = 0.0f;
    __syncthreads();
    if (tid == 0) {
        int a = 0;
        for (int i = 0; i < 16; i++) { sStart[i] = a; a += sCnt[i]; }
        sStart[16] = a;
    }
    __syncthreads();
    if (tid < 16) {
        int pos = sStart[tid];
        for (int n = 0; n < 32; n++) {
            if (relation_ids[(b0 + tid) * NN + n] == r) {
                int v = virtual_mask[(b0 + tid) * NN + n] ? 1 : 0;
                sList[pos++] = n | (v << 6) | (tid << 8);
            }
        }
    }

    // stage B: W_f[r][g0..g0+127][k0..k0+127] -> split fp16, [g][k] stride 136
    {
        __half* bh = (__half*)(dsm + BHI);
        __half* bl = (__half*)(dsm + BLO);
        for (int i = tid; i < 128 * 64; i += 256) {
            int gg = i >> 6, k = (i & 63) * 2;
            float2 v = *(const float2*)&W_f[(size_t)r * 65536 + (size_t)(g0 + gg) * 256 + k0 + k];
            __half hx = __float2half_rn(v.x);
            __half hy = __float2half_rn(v.y);
            *(uint32_t*)&bh[gg * BSTR + k] = pkhf(v.x, v.y);
            *(uint32_t*)&bl[gg * BSTR + k] =
                pkhf(v.x - __half2float(hx), v.y - __half2float(hy));
        }
    }
    __syncthreads();

    const int count = sStart[16];
    const int ntiles = (count + 31) >> 5;
    const uint32_t smb = smem_u32(dsm);
    const int gcol = tid & 127, hf = tid >> 7;
    const float bfk = (khalf == 0) ? b_f[r * HH + g0 + gcol] : 0.0f;
    const int tIdx = lane >> 3, rsub = lane & 7;

    // ---- preload B-hi fragments for this warp's 16 n-cols (invariant) ----
    uint32_t bhreg[8][4];
    {
        int n = warp * 16 + ((tIdx & 2) ? 8 : 0) + rsub;
        #pragma unroll
        for (int kt = 0; kt < 8; kt++) {
            int k = kt * 16 + ((tIdx & 1) ? 8 : 0);
            ldsm4(bhreg[kt], smb + BHI + (uint32_t)(n * BSTR + k) * 2u);
        }
    }

    for (int t = 0; t < ntiles; t++) {
        // ---- stage A tile: 32 children x 128 k, fp16 hi only (overwrites prev F) ----
        {
            int s = tid >> 3, seg = tid & 7;
            int gs = t * 32 + s;
            const float* src = nullptr;
            if (gs < count) {
                int e = sList[gs];
                src = &child_h[((size_t)(b0 + (e >> 8)) * NN + (e & 63)) * HH + k0 + seg * 16];
            }
            __half* ah = (__half*)(dsm + ASM);
            #pragma unroll
            for (int j = 0; j < 4; j++) {
                float4 v = src ? *(const float4*)(src + j * 4) : make_float4(0.f, 0.f, 0.f, 0.f);
                int col = seg * 16 + j * 4;
                *(uint32_t*)&ah[s * BSTR + col]     = pkhf(v.x, v.y);
                *(uint32_t*)&ah[s * BSTR + col + 2] = pkhf(v.z, v.w);
            }
        }

        // ---- early-issue child_c loads into registers (consumed in fold) ----
        float ccv[16];
        {
            int sbase = t * 32 + hf * 16;
            #pragma unroll
            for (int j = 0; j < 16; j++) {
                int s = sbase + j;
                float v = 0.0f;
                if (s < count) {
                    int e = sList[s];
                    v = child_c[((size_t)(b0 + (e >> 8)) * NN + (e & 63)) * HH + g0 + gcol];
                }
                ccv[j] = v;
            }
        }
        __syncthreads();

        // ---- mma: Ah·Bh + Ah·Bl (2 terms, fp16) ----
        float d[2][2][4];
        #pragma unroll
        for (int mt = 0; mt < 2; mt++)
            #pragma unroll
            for (int nt = 0; nt < 2; nt++)
                #pragma unroll
                for (int q = 0; q < 4; q++) d[mt][nt][q] = 0.0f;

        {
            const uint32_t ahb = smb + ASM;
            const uint32_t blb = smb + BLO;
            int brow = warp * 16 + ((tIdx & 2) ? 8 : 0) + rsub;
            #pragma unroll
            for (int kt = 0; kt < 8; kt++) {
                int kk = kt * 16;
                int kfrag = kk + ((tIdx & 1) ? 8 : 0);
                uint32_t areg[2][4], blreg[4];
                #pragma unroll
                for (int mt = 0; mt < 2; mt++) {
                    int row = mt * 16 + ((tIdx & 1) ? 8 : 0) + rsub;
                    int col = kk + ((tIdx & 2) ? 8 : 0);
                    ldsm4(areg[mt], ahb + (uint32_t)(row * BSTR + col) * 2u);
                }
                ldsm4(blreg, blb + (uint32_t)(brow * BSTR + kfrag) * 2u);
                #pragma unroll
                for (int mt = 0; mt < 2; mt++)
                    #pragma unroll
                    for (int nt = 0; nt < 2; nt++) {
                        mma16816h(d[mt][nt], areg[mt], &bhreg[kt][nt * 2]);
                        mma16816h(d[mt][nt], areg[mt], &blreg[nt * 2]);
                    }
            }
        }
        __syncthreads();   // all warps done reading A before F overlays it

        // ---- write F tile into the (now dead) A region ----
        {
            float* F = (float*)(dsm + ASM);
            int arow = lane >> 2, acol = (lane & 3) * 2;
            #pragma unroll
            for (int mt = 0; mt < 2; mt++)
                #pragma unroll
                for (int nt = 0; nt < 2; nt++) {
                    int col = warp * 16 + nt * 8 + acol;
                    F[(mt * 16 + arow) * FSTR + col]         = d[mt][nt][0];
                    F[(mt * 16 + arow) * FSTR + col + 1]     = d[mt][nt][1];
                    F[(mt * 16 + arow + 8) * FSTR + col]     = d[mt][nt][2];
                    F[(mt * 16 + arow + 8) * FSTR + col + 1] = d[mt][nt][3];
                }
        }
        __syncthreads();

        // ---- fold into per-batch partial csum ----
        {
            const float* F = (const float*)(dsm + ASM);
            int sbase = t * 32 + hf * 16;
            int smax = min(16, count - sbase);
            for (int j = 0; j < smax; j++) {
                int e = sList[sbase + j];
                int bl = e >> 8;
                float dcy = ((e >> 6) & 1) ? VDECAY : 1.0f;
                float Fv = F[(hf * 16 + j) * FSTR + gcol];
                shCS[hf][bl][gcol] += (Fv * dcy + bfk) * (ccv[j] * dcy);
            }
        }
        __syncthreads();
    }

    {
        int slot = r * 2 + khalf;
        for (int i = tid; i < 16 * 128; i += 256) {
            int bl = i >> 7, g = i & 127;
            g_csum6[((size_t)slot * BB + b0 + bl) * HH + g0 + g] =
                shCS[0][bl][g] + shCS[1][bl][g];
        }
    }
}

// ---------------- gates: scalar FFMA + cp.async weights (16 batches/block) ----
#define G_SMEM 81920
__global__ __launch_bounds__(256) void gates_kernel(
    const float* __restrict__ b_i, const float* __restrict__ b_o,
    const float* __restrict__ b_u, float* __restrict__ out)
{
    extern __shared__ char gsm[];
    float* sh_comb = (float*)gsm;             // [16][512]
    float* sh_w    = (float*)(gsm + 32768);   // [2][3*2048]

    const int b0 = blockIdx.x * 16, tid = threadIdx.x, g = tid;

    for (int idx = tid; idx < 16 * 512; idx += 256)
        sh_comb[idx] = g_comb[(size_t)b0 * 512 + idx];

    auto stage = [&](int c, int buf) {
        float* dst = sh_w + buf * 6144;
        for (int i = tid; i < 1536; i += 256) {
            int j = i * 4;
            int g4 = j & 255, kk = (j >> 8) & 7, gate = j >> 11;
            cpa16(dst + j, &g_WgT[((size_t)gate * 512 + c * 8 + kk) * 256 + g4]);
        }
        CPA_COMMIT();
    };

    float ai[16], ao[16], au[16];
    #pragma unroll
    for (int m = 0; m < 16; m++) { ai[m] = 0.f; ao[m] = 0.f; au[m] = 0.f; }

    stage(0, 0);
    __syncthreads();

    #pragma unroll 1
    for (int c = 0; c < 64; c++) {
        int buf = c & 1;
        if (c < 63) stage(c + 1, buf ^ 1);
        else CPA_COMMIT();
        cpa_wait<1>();
        __syncthreads();
        const float* wb = sh_w + buf * 6144;
        #pragma unroll
        for (int kk2 = 0; kk2 < 4; kk2++) {
            int k = c * 8 + kk2 * 2;
            float wi0 = wb[(kk2 * 2) * 256 + g],        wi1 = wb[(kk2 * 2 + 1) * 256 + g];
            float wo0 = wb[2048 + (kk2 * 2) * 256 + g], wo1 = wb[2048 + (kk2 * 2 + 1) * 256 + g];
            float wu0 = wb[4096 + (kk2 * 2) * 256 + g], wu1 = wb[4096 + (kk2 * 2 + 1) * 256 + g];
            #pragma unroll
            for (int m = 0; m < 16; m++) {
                float2 cm = *(const float2*)&sh_comb[m * 512 + k];
                ai[m] = fmaf(cm.x, wi0, fmaf(cm.y, wi1, ai[m]));
                ao[m] = fmaf(cm.x, wo0, fmaf(cm.y, wo1, ao[m]));
                au[m] = fmaf(cm.x, wu0, fmaf(cm.y, wu1, au[m]));
            }
        }
        __syncthreads();
    }
    cpa_wait<0>();

    const float biv = b_i[g], bov = b_o[g], buv = b_u[g];
    #pragma unroll
    for (int m = 0; m < 16; m++) {
        int b = b0 + m;
        float cs = 0.0f;
        #pragma unroll
        for (int slot = 0; slot < 6; slot++)
            cs += g_csum6[((size_t)slot * BB + b) * HH + g];
        float iv = 1.0f / (1.0f + expf(-(ai[m] + biv)));
        float ov = 1.0f / (1.0f + expf(-(ao[m] + bov)));
        float uv = tanhf(au[m] + buv);
        float cv = fmaf(iv, uv, cs);
        float hv = ov * tanhf(cv);
        out[(size_t)b * HH + g]        = hv;   // h first
        out[(size_t)(BB + b) * HH + g] = cv;   // then c
    }
}

// ---------------- launch ----------------
extern "C" void kernel_launch(void* const* d_in, const int* in_sizes, int n_in,
                              void* d_out, int out_size) {
    const float* input_vec = (const float*)d_in[0];
    const float* child_h   = (const float*)d_in[1];
    const float* child_c   = (const float*)d_in[2];
    const int*   rid       = (const int*)d_in[3];
    const int*   vmask     = (const int*)d_in[4];
    const float* rel_emb   = (const float*)d_in[5];
    const float* W_i = (const float*)d_in[6];
    const float* b_i = (const float*)d_in[7];
    const float* W_f = (const float*)d_in[8];
    const float* b_f = (const float*)d_in[9];
    const float* W_o = (const float*)d_in[10];
    const float* b_o = (const float*)d_in[11];
    const float* W_u = (const float*)d_in[12];
    const float* b_u = (const float*)d_in[13];
    const float* w_att = (const float*)d_in[14];
    const float* b_att = (const float*)d_in[15];
    float* out = (float*)d_out;

    cudaFuncSetAttribute(fgemm_mma,    cudaFuncAttributeMaxDynamicSharedMemorySize, FG_DYN);
    cudaFuncSetAttribute(gates_kernel, cudaFuncAttributeMaxDynamicSharedMemorySize, G_SMEM);

    prep_kernel<<<1536, 256>>>(W_i, W_o, W_u);
    dim3 fg(BB / 16, RR, 4);
    fgemm_mma<<<fg, 256, FG_DYN>>>(child_h, child_c, rid, vmask, W_f, b_f);
    attn_kernel<<<BB, 256>>>(input_vec, child_h, rid, vmask, rel_emb, w_att, b_att);
    gates_kernel<<<BB / 16, 256, G_SMEM>>>(b_i, b_o, b_u, out);
}

// round 14
// speedup vs baseline: 3.2063x; 1.1338x over previous
#include <cuda_runtime.h>
#include <cuda_fp16.h>
#include <cstdint>
#include <math.h>

#define BB 4096
#define NN 32
#define HH 256
#define RR 3
#define VDECAY 0.7f

// ---------------- device scratch ----------------
__device__ float  g_WgT[3 * 512 * HH];       // [gate][k][g]
__device__ float  g_comb[BB * 512];          // [b][input | child_h_sum]
__device__ float  g_csum6[6 * BB * HH];      // [r*2+khalf][b][g] partial csum
__device__ __half g_chH[(size_t)BB * NN * HH];   // child_h as fp16
__device__ __half g_WfH[RR * HH * HH];       // W_f fp16 hi
__device__ __half g_WfL[RR * HH * HH];       // W_f fp16 lo

// ---------------- helpers ----------------
__device__ __forceinline__ uint32_t smem_u32(const void* p) {
    uint32_t a;
    asm("{ .reg .u64 t; cvta.to.shared.u64 t, %1; cvt.u32.u64 %0, t; }" : "=r"(a) : "l"(p));
    return a;
}
__device__ __forceinline__ void ldsm4(uint32_t* r, uint32_t addr) {
    asm volatile("ldmatrix.sync.aligned.m8n8.x4.shared.b16 {%0,%1,%2,%3}, [%4];"
                 : "=r"(r[0]), "=r"(r[1]), "=r"(r[2]), "=r"(r[3]) : "r"(addr));
}
__device__ __forceinline__ void mma16816h(float* d, const uint32_t* a, const uint32_t* b) {
    asm volatile("mma.sync.aligned.m16n8k16.row.col.f32.f16.f16.f32 "
                 "{%0,%1,%2,%3},{%4,%5,%6,%7},{%8,%9},{%0,%1,%2,%3};"
                 : "+f"(d[0]), "+f"(d[1]), "+f"(d[2]), "+f"(d[3])
                 : "r"(a[0]), "r"(a[1]), "r"(a[2]), "r"(a[3]), "r"(b[0]), "r"(b[1]));
}
__device__ __forceinline__ uint32_t pkhf(float x, float y) {
    __half2 t = __floats2half2_rn(x, y);
    return *(uint32_t*)&t;
}
__device__ __forceinline__ void cpa16(void* sdst, const void* gsrc) {
    unsigned s = (unsigned)__cvta_generic_to_shared(sdst);
    asm volatile("cp.async.ca.shared.global [%0], [%1], 16;" :: "r"(s), "l"(gsrc) : "memory");
}
#define CPA_COMMIT() asm volatile("cp.async.commit_group;" ::: "memory")
template <int N> __device__ __forceinline__ void cpa_wait() {
    asm volatile("cp.async.wait_group %0;" :: "n"(N) : "memory");
}

// ---------------- prep: gate transpose + W_f fp16 split ----------------
__global__ void prep_kernel(const float* __restrict__ Wi,
                            const float* __restrict__ Wo,
                            const float* __restrict__ Wu,
                            const float* __restrict__ Wf) {
    int idx = blockIdx.x * blockDim.x + threadIdx.x;
    const int NG = 3 * 512 * HH;     // 393216
    const int NF = RR * HH * HH;     // 196608
    if (idx < NG) {
        int g = idx & 255, t = idx >> 8, k = t & 511, gate = t >> 9;
        const float* W = (gate == 0) ? Wi : ((gate == 1) ? Wo : Wu);
        g_WgT[idx] = W[g * 512 + k];
    } else if (idx < NG + NF) {
        int j = idx - NG;
        float v = Wf[j];
        __half h = __float2half_rn(v);
        g_WfH[j] = h;
        g_WfL[j] = __float2half_rn(v - __half2float(h));
    }
}

// ---------------- prep: child_h -> fp16 (exact 16384 blocks) ----------------
__global__ void prep_ch(const float* __restrict__ ch) {
    size_t i = ((size_t)blockIdx.x * 256 + threadIdx.x) * 8;
    float4 a = *(const float4*)(ch + i);
    float4 b = *(const float4*)(ch + i + 4);
    uint4 o;
    o.x = pkhf(a.x, a.y);
    o.y = pkhf(a.z, a.w);
    o.z = pkhf(b.x, b.y);
    o.w = pkhf(b.z, b.w);
    *(uint4*)(&g_chH[i]) = o;
}

// ---------------- attention + comb (validated) ----------------
#define CHS 260
__global__ __launch_bounds__(256) void attn_kernel(
    const float* __restrict__ input_vec, const float* __restrict__ child_h,
    const int* __restrict__ relation_ids, const int* __restrict__ virtual_mask,
    const float* __restrict__ rel_emb, const float* __restrict__ w_att,
    const float* __restrict__ b_att)
{
    __shared__ float sh_ch[NN * CHS];
    __shared__ int   sh_rid[NN];
    __shared__ float sh_decay[NN], sh_score[NN], sh_attn[NN];
    const int b = blockIdx.x, tid = threadIdx.x, lane = tid & 31, warp = tid >> 5;

    if (tid < NN) {
        sh_rid[tid]   = relation_ids[b * NN + tid];
        sh_decay[tid] = virtual_mask[b * NN + tid] ? VDECAY : 1.0f;
    }
    __syncthreads();
    {
        const float* chb = child_h + (size_t)b * NN * HH;
        for (int idx = tid; idx < NN * HH; idx += 256) {
            int n = idx >> 8, h = idx & 255;
            sh_ch[n * CHS + h] = chb[n * HH + h] * sh_decay[n];
        }
    }
    __syncthreads();
    {
        float batt = b_att[0];
        #pragma unroll
        for (int c = 0; c < 4; c++) {
            int p = warp * 4 + c;
            int r = sh_rid[p];
            float s = 0.0f;
            #pragma unroll
            for (int j = 0; j < 8; j++) {
                int h = j * 32 + lane;
                s = fmaf(rel_emb[r * HH + h] + sh_ch[p * CHS + h], w_att[h], s);
            }
            #pragma unroll
            for (int off = 16; off; off >>= 1) s += __shfl_xor_sync(0xffffffffu, s, off);
            if (lane == 0) sh_score[p] = s + batt;
        }
    }
    __syncthreads();
    if (warp == 0) {
        float v = sh_score[lane], m = v;
        #pragma unroll
        for (int off = 16; off; off >>= 1) m = fmaxf(m, __shfl_xor_sync(0xffffffffu, m, off));
        float e = expf(v - m), s = e;
        #pragma unroll
        for (int off = 16; off; off >>= 1) s += __shfl_xor_sync(0xffffffffu, s, off);
        sh_attn[lane] = e / s;
    }
    __syncthreads();
    const int g = tid;
    float hs = 0.0f;
    #pragma unroll
    for (int p = 0; p < NN; p++) hs = fmaf(sh_attn[p], sh_ch[p * CHS + g], hs);
    g_comb[b * 512 + 256 + g] = hs;
    g_comb[b * 512 + g]       = input_vec[(size_t)b * HH + g];
}

// ---------------- fgemm_mma: fp16 2-term, cp.async pipelined ----------------
// grid (256, 3, 4): z = khalf*2 + ghalf. block 256 = 8 warps, 2 CTAs/SM.
// dyn smem 69632 B:
//   [0, 34816)      Bh staging -> after bhreg preload reused as:
//                     Abuf0 @0 (8704), Abuf1 @8704 (8704), F @17408 (16896)
//   [34816, 69632)  Bl (persistent)
#define BSTR 136
#define BL_OFF 34816
#define AB_OFF(buf) ((buf) * 8704)
#define F_OFF 17408
#define FSTR 132
#define FG_DYN 69632

__global__ __launch_bounds__(256, 2) void fgemm_mma(
    const float* __restrict__ child_c,
    const int*   __restrict__ relation_ids,
    const int*   __restrict__ virtual_mask,
    const float* __restrict__ b_f)
{
    extern __shared__ char dsm[];
    __shared__ int   sList[512], sStart[17], sCnt[16];
    __shared__ float shCS[2][16][129];

    const int tid = threadIdx.x, lane = tid & 31, warp = tid >> 5;
    const int b0 = blockIdx.x * 16, r = blockIdx.y;
    const int ghalf = blockIdx.z & 1, khalf = blockIdx.z >> 1;
    const int g0 = ghalf * 128, k0 = khalf * 128;

    // compaction: counts -> prefix -> ordered fill
    if (tid < 16) {
        int c = 0;
        for (int n = 0; n < 32; n++) c += (relation_ids[(b0 + tid) * NN + n] == r);
        sCnt[tid] = c;
    }
    for (int i = tid; i < 2 * 16 * 129; i += 256) ((float*)shCS)[i] = 0.0f;
    __syncthreads();
    if (tid == 0) {
        int a = 0;
        for (int i = 0; i < 16; i++) { sStart[i] = a; a += sCnt[i]; }
        sStart[16] = a;
    }
    __syncthreads();
    if (tid < 16) {
        int pos = sStart[tid];
        for (int n = 0; n < 32; n++) {
            if (relation_ids[(b0 + tid) * NN + n] == r) {
                int v = virtual_mask[(b0 + tid) * NN + n] ? 1 : 0;
                sList[pos++] = n | (v << 6) | (tid << 8);
            }
        }
    }
    __syncthreads();

    // ---- stage B hi+lo via cp.async from pre-split fp16 ----
    for (int j = tid; j < 4096; j += 256) {
        int hl = j >> 11, jj = j & 2047;
        int gg = jj >> 4, q = jj & 15;
        const __half* src = (hl ? g_WfL : g_WfH) +
            (size_t)r * 65536 + (size_t)(g0 + gg) * 256 + k0 + q * 8;
        cpa16(dsm + hl * BL_OFF + (gg * BSTR + q * 8) * 2, src);
    }
    CPA_COMMIT();
    cpa_wait<0>();
    __syncthreads();

    const int count = sStart[16];
    const int ntiles = (count + 31) >> 5;
    const uint32_t smb = smem_u32(dsm);
    const int gcol = tid & 127, hf = tid >> 7;
    const float bfk = (khalf == 0) ? b_f[r * HH + g0 + gcol] : 0.0f;
    const int tIdx = lane >> 3, rsub = lane & 7;

    // ---- preload B-hi fragments (then Bh smem region is dead) ----
    uint32_t bhreg[8][4];
    {
        int n = warp * 16 + ((tIdx & 2) ? 8 : 0) + rsub;
        #pragma unroll
        for (int kt = 0; kt < 8; kt++) {
            int k = kt * 16 + ((tIdx & 1) ? 8 : 0);
            ldsm4(bhreg[kt], smb + (uint32_t)(n * BSTR + k) * 2u);
        }
    }
    __syncthreads();   // all warps done reading Bh; region now A/F scratch

    // ---- A staging helper: 32 children x 128 k fp16, pure cp.async ----
    auto stageA = [&](int tt, int buf) {
        for (int i = tid; i < 512; i += 256) {
            int s = i >> 4, q = i & 15;
            int gs = tt * 32 + s;
            if (gs < count) {
                int e = sList[gs];
                const __half* src = g_chH +
                    (((size_t)(b0 + (e >> 8))) * NN + (e & 63)) * HH + k0 + q * 8;
                cpa16(dsm + AB_OFF(buf) + (s * BSTR + q * 8) * 2, src);
            }
        }
        CPA_COMMIT();
    };

    if (ntiles > 0) stageA(0, 0);

    for (int t = 0; t < ntiles; t++) {
        const int buf = t & 1;
        cpa_wait<0>();
        __syncthreads();   // A(t) visible to all; fold(t-1) complete

        if (t + 1 < ntiles) stageA(t + 1, buf ^ 1);   // overlaps MMA(t)

        // early-issue child_c loads (consumed in fold)
        float ccv[16];
        {
            int sbase = t * 32 + hf * 16;
            #pragma unroll
            for (int j = 0; j < 16; j++) {
                int s = sbase + j;
                float v = 0.0f;
                if (s < count) {
                    int e = sList[s];
                    v = child_c[((size_t)(b0 + (e >> 8)) * NN + (e & 63)) * HH + g0 + gcol];
                }
                ccv[j] = v;
            }
        }

        // ---- mma: Ah·Bh (regs) + Ah·Bl (smem) ----
        float d[2][2][4];
        #pragma unroll
        for (int mt = 0; mt < 2; mt++)
            #pragma unroll
            for (int nt = 0; nt < 2; nt++)
                #pragma unroll
                for (int q = 0; q < 4; q++) d[mt][nt][q] = 0.0f;
        {
            const uint32_t ahb = smb + AB_OFF(buf);
            const uint32_t blb = smb + BL_OFF;
            int brow = warp * 16 + ((tIdx & 2) ? 8 : 0) + rsub;
            #pragma unroll
            for (int kt = 0; kt < 8; kt++) {
                int kk = kt * 16;
                int kfrag = kk + ((tIdx & 1) ? 8 : 0);
                uint32_t areg[2][4], blreg[4];
                #pragma unroll
                for (int mt = 0; mt < 2; mt++) {
                    int row = mt * 16 + ((tIdx & 1) ? 8 : 0) + rsub;
                    int col = kk + ((tIdx & 2) ? 8 : 0);
                    ldsm4(areg[mt], ahb + (uint32_t)(row * BSTR + col) * 2u);
                }
                ldsm4(blreg, blb + (uint32_t)(brow * BSTR + kfrag) * 2u);
                #pragma unroll
                for (int mt = 0; mt < 2; mt++)
                    #pragma unroll
                    for (int nt = 0; nt < 2; nt++) {
                        mma16816h(d[mt][nt], areg[mt], &bhreg[kt][nt * 2]);
                        mma16816h(d[mt][nt], areg[mt], &blreg[nt * 2]);
                    }
            }
        }

        // ---- write F tile (separate region; no pre-sync needed) ----
        {
            float* F = (float*)(dsm + F_OFF);
            int arow = lane >> 2, acol = (lane & 3) * 2;
            #pragma unroll
            for (int mt = 0; mt < 2; mt++)
                #pragma unroll
                for (int nt = 0; nt < 2; nt++) {
                    int col = warp * 16 + nt * 8 + acol;
                    F[(mt * 16 + arow) * FSTR + col]         = d[mt][nt][0];
                    F[(mt * 16 + arow) * FSTR + col + 1]     = d[mt][nt][1];
                    F[(mt * 16 + arow + 8) * FSTR + col]     = d[mt][nt][2];
                    F[(mt * 16 + arow + 8) * FSTR + col + 1] = d[mt][nt][3];
                }
        }
        __syncthreads();

        // ---- fold into per-batch partial csum (thread-private columns) ----
        {
            const float* F = (const float*)(dsm + F_OFF);
            int sbase = t * 32 + hf * 16;
            int smax = min(16, count - sbase);
            for (int j = 0; j < smax; j++) {
                int e = sList[sbase + j];
                int bl = e >> 8;
                float dcy = ((e >> 6) & 1) ? VDECAY : 1.0f;
                float Fv = F[(hf * 16 + j) * FSTR + gcol];
                shCS[hf][bl][gcol] += (Fv * dcy + bfk) * (ccv[j] * dcy);
            }
        }
        // next iteration's top __syncthreads separates fold(t) from F-write(t+1)
    }

    {
        int slot = r * 2 + khalf;
        __syncthreads();
        for (int i = tid; i < 16 * 128; i += 256) {
            int bl = i >> 7, g = i & 127;
            g_csum6[((size_t)slot * BB + b0 + bl) * HH + g0 + g] =
                shCS[0][bl][g] + shCS[1][bl][g];
        }
    }
}

// ---------------- gates: scalar FFMA + cp.async weights (16 batches/block) ----
#define G_SMEM 81920
__global__ __launch_bounds__(256) void gates_kernel(
    const float* __restrict__ b_i, const float* __restrict__ b_o,
    const float* __restrict__ b_u, float* __restrict__ out)
{
    extern __shared__ char gsm[];
    float* sh_comb = (float*)gsm;             // [16][512]
    float* sh_w    = (float*)(gsm + 32768);   // [2][3*2048]

    const int b0 = blockIdx.x * 16, tid = threadIdx.x, g = tid;

    for (int idx = tid; idx < 16 * 512; idx += 256)
        sh_comb[idx] = g_comb[(size_t)b0 * 512 + idx];

    auto stage = [&](int c, int buf) {
        float* dst = sh_w + buf * 6144;
        for (int i = tid; i < 1536; i += 256) {
            int j = i * 4;
            int g4 = j & 255, kk = (j >> 8) & 7, gate = j >> 11;
            cpa16(dst + j, &g_WgT[((size_t)gate * 512 + c * 8 + kk) * 256 + g4]);
        }
        CPA_COMMIT();
    };

    float ai[16], ao[16], au[16];
    #pragma unroll
    for (int m = 0; m < 16; m++) { ai[m] = 0.f; ao[m] = 0.f; au[m] = 0.f; }

    stage(0, 0);
    __syncthreads();

    #pragma unroll 1
    for (int c = 0; c < 64; c++) {
        int buf = c & 1;
        if (c < 63) stage(c + 1, buf ^ 1);
        else CPA_COMMIT();
        cpa_wait<1>();
        __syncthreads();
        const float* wb = sh_w + buf * 6144;
        #pragma unroll
        for (int kk2 = 0; kk2 < 4; kk2++) {
            int k = c * 8 + kk2 * 2;
            float wi0 = wb[(kk2 * 2) * 256 + g],        wi1 = wb[(kk2 * 2 + 1) * 256 + g];
            float wo0 = wb[2048 + (kk2 * 2) * 256 + g], wo1 = wb[2048 + (kk2 * 2 + 1) * 256 + g];
            float wu0 = wb[4096 + (kk2 * 2) * 256 + g], wu1 = wb[4096 + (kk2 * 2 + 1) * 256 + g];
            #pragma unroll
            for (int m = 0; m < 16; m++) {
                float2 cm = *(const float2*)&sh_comb[m * 512 + k];
                ai[m] = fmaf(cm.x, wi0, fmaf(cm.y, wi1, ai[m]));
                ao[m] = fmaf(cm.x, wo0, fmaf(cm.y, wo1, ao[m]));
                au[m] = fmaf(cm.x, wu0, fmaf(cm.y, wu1, au[m]));
            }
        }
        __syncthreads();
    }
    cpa_wait<0>();

    const float biv = b_i[g], bov = b_o[g], buv = b_u[g];
    #pragma unroll
    for (int m = 0; m < 16; m++) {
        int b = b0 + m;
        float cs = 0.0f;
        #pragma unroll
        for (int slot = 0; slot < 6; slot++)
            cs += g_csum6[((size_t)slot * BB + b) * HH + g];
        float iv = 1.0f / (1.0f + expf(-(ai[m] + biv)));
        float ov = 1.0f / (1.0f + expf(-(ao[m] + bov)));
        float uv = tanhf(au[m] + buv);
        float cv = fmaf(iv, uv, cs);
        float hv = ov * tanhf(cv);
        out[(size_t)b * HH + g]        = hv;   // h first
        out[(size_t)(BB + b) * HH + g] = cv;   // then c
    }
}

// ---------------- launch ----------------
extern "C" void kernel_launch(void* const* d_in, const int* in_sizes, int n_in,
                              void* d_out, int out_size) {
    const float* input_vec = (const float*)d_in[0];
    const float* child_h   = (const float*)d_in[1];
    const float* child_c   = (const float*)d_in[2];
    const int*   rid       = (const int*)d_in[3];
    const int*   vmask     = (const int*)d_in[4];
    const float* rel_emb   = (const float*)d_in[5];
    const float* W_i = (const float*)d_in[6];
    const float* b_i = (const float*)d_in[7];
    const float* W_f = (const float*)d_in[8];
    const float* b_f = (const float*)d_in[9];
    const float* W_o = (const float*)d_in[10];
    const float* b_o = (const float*)d_in[11];
    const float* W_u = (const float*)d_in[12];
    const float* b_u = (const float*)d_in[13];
    const float* w_att = (const float*)d_in[14];
    const float* b_att = (const float*)d_in[15];
    float* out = (float*)d_out;

    cudaFuncSetAttribute(fgemm_mma,    cudaFuncAttributeMaxDynamicSharedMemorySize, FG_DYN);
    cudaFuncSetAttribute(gates_kernel, cudaFuncAttributeMaxDynamicSharedMemorySize, G_SMEM);

    prep_kernel<<<2304, 256>>>(W_i, W_o, W_u, W_f);
    prep_ch<<<16384, 256>>>(child_h);
    dim3 fg(BB / 16, RR, 4);
    fgemm_mma<<<fg, 256, FG_DYN>>>(child_c, rid, vmask, b_f);
    attn_kernel<<<BB, 256>>>(input_vec, child_h, rid, vmask, rel_emb, w_att, b_att);
    gates_kernel<<<BB / 16, 256, G_SMEM>>>(b_i, b_o, b_u, out);
}

// round 15
// speedup vs baseline: 3.8347x; 1.1960x over previous
#include <cuda_runtime.h>
#include <cuda_fp16.h>
#include <cstdint>
#include <math.h>

#define BB 4096
#define NN 32
#define HH 256
#define RR 3
#define VDECAY 0.7f

// ---------------- device scratch ----------------
__device__ float  g_csum6[6 * BB * HH];        // [r*2+khalf][b][g] partial csum
__device__ float  g_pre[3 * BB * HH];          // gate preacts [gate][b][g]
__device__ __half g_chH[(size_t)BB * NN * HH]; // child_h fp16 (raw)
__device__ __half g_combH[BB * 512];           // comb fp16 hi
__device__ __half g_combL[BB * 512];           // comb fp16 lo
__device__ __half g_WfH[RR * HH * HH];         // W_f fp16 hi
__device__ __half g_WfL[RR * HH * HH];         // W_f fp16 lo
__device__ __half g_WgH[3 * HH * 512];         // gate W fp16 hi [gate][g][k]
__device__ __half g_WgL[3 * HH * 512];         // gate W fp16 lo

// ---------------- helpers ----------------
__device__ __forceinline__ uint32_t smem_u32(const void* p) {
    uint32_t a;
    asm("{ .reg .u64 t; cvta.to.shared.u64 t, %1; cvt.u32.u64 %0, t; }" : "=r"(a) : "l"(p));
    return a;
}
__device__ __forceinline__ void ldsm4(uint32_t* r, uint32_t addr) {
    asm volatile("ldmatrix.sync.aligned.m8n8.x4.shared.b16 {%0,%1,%2,%3}, [%4];"
                 : "=r"(r[0]), "=r"(r[1]), "=r"(r[2]), "=r"(r[3]) : "r"(addr));
}
__device__ __forceinline__ void mma16816h(float* d, const uint32_t* a, const uint32_t* b) {
    asm volatile("mma.sync.aligned.m16n8k16.row.col.f32.f16.f16.f32 "
                 "{%0,%1,%2,%3},{%4,%5,%6,%7},{%8,%9},{%0,%1,%2,%3};"
                 : "+f"(d[0]), "+f"(d[1]), "+f"(d[2]), "+f"(d[3])
                 : "r"(a[0]), "r"(a[1]), "r"(a[2]), "r"(a[3]), "r"(b[0]), "r"(b[1]));
}
__device__ __forceinline__ uint32_t pkhf(float x, float y) {
    __half2 t = __floats2half2_rn(x, y);
    return *(uint32_t*)&t;
}
__device__ __forceinline__ void cpa16(void* sdst, const void* gsrc) {
    unsigned s = (unsigned)__cvta_generic_to_shared(sdst);
    asm volatile("cp.async.ca.shared.global [%0], [%1], 16;" :: "r"(s), "l"(gsrc) : "memory");
}
#define CPA_COMMIT() asm volatile("cp.async.commit_group;" ::: "memory")
template <int N> __device__ __forceinline__ void cpa_wait() {
    asm volatile("cp.async.wait_group %0;" :: "n"(N) : "memory");
}

// ---------------- prep: fp16 splits for W_f and gate weights ----------------
__global__ void prep_kernel(const float* __restrict__ Wi,
                            const float* __restrict__ Wo,
                            const float* __restrict__ Wu,
                            const float* __restrict__ Wf) {
    int idx = blockIdx.x * blockDim.x + threadIdx.x;
    const int NWG = 3 * HH * 512;    // 393216
    const int NF  = RR * HH * HH;    // 196608
    if (idx < NWG) {
        int j = idx & (HH * 512 - 1);
        int gate = idx >> 17;
        const float* W = (gate == 0) ? Wi : ((gate == 1) ? Wo : Wu);
        float v = W[j];
        __half h = __float2half_rn(v);
        g_WgH[idx] = h;
        g_WgL[idx] = __float2half_rn(v - __half2float(h));
    } else if (idx < NWG + NF) {
        int j = idx - NWG;
        float v = Wf[j];
        __half h = __float2half_rn(v);
        g_WfH[j] = h;
        g_WfL[j] = __float2half_rn(v - __half2float(h));
    }
}

// ---------------- attention + comb + fp16 conversions ----------------
#define CHS 260
__global__ __launch_bounds__(256) void attn_kernel(
    const float* __restrict__ input_vec, const float* __restrict__ child_h,
    const int* __restrict__ relation_ids, const int* __restrict__ virtual_mask,
    const float* __restrict__ rel_emb, const float* __restrict__ w_att,
    const float* __restrict__ b_att)
{
    __shared__ float sh_ch[NN * CHS];
    __shared__ int   sh_rid[NN];
    __shared__ float sh_decay[NN], sh_score[NN], sh_attn[NN];
    const int b = blockIdx.x, tid = threadIdx.x, lane = tid & 31, warp = tid >> 5;

    if (tid < NN) {
        sh_rid[tid]   = relation_ids[b * NN + tid];
        sh_decay[tid] = virtual_mask[b * NN + tid] ? VDECAY : 1.0f;
    }
    __syncthreads();
    {
        const float* chb = child_h + (size_t)b * NN * HH;
        uint32_t* chH2 = (uint32_t*)(g_chH + (size_t)b * NN * HH);
        for (int i2 = tid; i2 < NN * 128; i2 += 256) {
            int n = i2 >> 7, h2 = (i2 & 127) * 2;
            float2 v = *(const float2*)(chb + n * HH + h2);
            float d = sh_decay[n];
            sh_ch[n * CHS + h2]     = v.x * d;
            sh_ch[n * CHS + h2 + 1] = v.y * d;
            chH2[i2 >> 7 << 7 | (i2 & 127)] = pkhf(v.x, v.y);   // = chH2[n*128 + h2/2]
        }
    }
    __syncthreads();
    {
        float batt = b_att[0];
        #pragma unroll
        for (int c = 0; c < 4; c++) {
            int p = warp * 4 + c;
            int r = sh_rid[p];
            float s = 0.0f;
            #pragma unroll
            for (int j = 0; j < 8; j++) {
                int h = j * 32 + lane;
                s = fmaf(rel_emb[r * HH + h] + sh_ch[p * CHS + h], w_att[h], s);
            }
            #pragma unroll
            for (int off = 16; off; off >>= 1) s += __shfl_xor_sync(0xffffffffu, s, off);
            if (lane == 0) sh_score[p] = s + batt;
        }
    }
    __syncthreads();
    if (warp == 0) {
        float v = sh_score[lane], m = v;
        #pragma unroll
        for (int off = 16; off; off >>= 1) m = fmaxf(m, __shfl_xor_sync(0xffffffffu, m, off));
        float e = expf(v - m), s = e;
        #pragma unroll
        for (int off = 16; off; off >>= 1) s += __shfl_xor_sync(0xffffffffu, s, off);
        sh_attn[lane] = e / s;
    }
    __syncthreads();
    const int g = tid;
    float hs = 0.0f;
    #pragma unroll
    for (int p = 0; p < NN; p++) hs = fmaf(sh_attn[p], sh_ch[p * CHS + g], hs);
    float inv = input_vec[(size_t)b * HH + g];
    // comb fp16 split: [input | child_h_sum]
    __half ih = __float2half_rn(inv);
    __half hh = __float2half_rn(hs);
    g_combH[b * 512 + g]       = ih;
    g_combL[b * 512 + g]       = __float2half_rn(inv - __half2float(ih));
    g_combH[b * 512 + 256 + g] = hh;
    g_combL[b * 512 + 256 + g] = __float2half_rn(hs - __half2float(hh));
}

// ---------------- fgemm_mma: fp16 2-term, cp.async pipelined (R14, validated) ----
#define BSTR 136
#define BL_OFF 34816
#define AB_OFF(buf) ((buf) * 8704)
#define F_OFF 17408
#define FSTR 132
#define FG_DYN 69632

__global__ __launch_bounds__(256, 2) void fgemm_mma(
    const float* __restrict__ child_c,
    const int*   __restrict__ relation_ids,
    const int*   __restrict__ virtual_mask,
    const float* __restrict__ b_f)
{
    extern __shared__ char dsm[];
    __shared__ int   sList[512], sStart[17], sCnt[16];
    __shared__ float shCS[2][16][129];

    const int tid = threadIdx.x, lane = tid & 31, warp = tid >> 5;
    const int b0 = blockIdx.x * 16, r = blockIdx.y;
    const int ghalf = blockIdx.z & 1, khalf = blockIdx.z >> 1;
    const int g0 = ghalf * 128, k0 = khalf * 128;

    if (tid < 16) {
        int c = 0;
        for (int n = 0; n < 32; n++) c += (relation_ids[(b0 + tid) * NN + n] == r);
        sCnt[tid] = c;
    }
    for (int i = tid; i < 2 * 16 * 129; i += 256) ((float*)shCS)[i] = 0.0f;
    __syncthreads();
    if (tid == 0) {
        int a = 0;
        for (int i = 0; i < 16; i++) { sStart[i] = a; a += sCnt[i]; }
        sStart[16] = a;
    }
    __syncthreads();
    if (tid < 16) {
        int pos = sStart[tid];
        for (int n = 0; n < 32; n++) {
            if (relation_ids[(b0 + tid) * NN + n] == r) {
                int v = virtual_mask[(b0 + tid) * NN + n] ? 1 : 0;
                sList[pos++] = n | (v << 6) | (tid << 8);
            }
        }
    }
    __syncthreads();

    for (int j = tid; j < 4096; j += 256) {
        int hl = j >> 11, jj = j & 2047;
        int gg = jj >> 4, q = jj & 15;
        const __half* src = (hl ? g_WfL : g_WfH) +
            (size_t)r * 65536 + (size_t)(g0 + gg) * 256 + k0 + q * 8;
        cpa16(dsm + hl * BL_OFF + (gg * BSTR + q * 8) * 2, src);
    }
    CPA_COMMIT();
    cpa_wait<0>();
    __syncthreads();

    const int count = sStart[16];
    const int ntiles = (count + 31) >> 5;
    const uint32_t smb = smem_u32(dsm);
    const int gcol = tid & 127, hf = tid >> 7;
    const float bfk = (khalf == 0) ? b_f[r * HH + g0 + gcol] : 0.0f;
    const int tIdx = lane >> 3, rsub = lane & 7;

    uint32_t bhreg[8][4];
    {
        int n = warp * 16 + ((tIdx & 2) ? 8 : 0) + rsub;
        #pragma unroll
        for (int kt = 0; kt < 8; kt++) {
            int k = kt * 16 + ((tIdx & 1) ? 8 : 0);
            ldsm4(bhreg[kt], smb + (uint32_t)(n * BSTR + k) * 2u);
        }
    }
    __syncthreads();

    auto stageA = [&](int tt, int buf) {
        for (int i = tid; i < 512; i += 256) {
            int s = i >> 4, q = i & 15;
            int gs = tt * 32 + s;
            if (gs < count) {
                int e = sList[gs];
                const __half* src = g_chH +
                    (((size_t)(b0 + (e >> 8))) * NN + (e & 63)) * HH + k0 + q * 8;
                cpa16(dsm + AB_OFF(buf) + (s * BSTR + q * 8) * 2, src);
            }
        }
        CPA_COMMIT();
    };

    if (ntiles > 0) stageA(0, 0);

    for (int t = 0; t < ntiles; t++) {
        const int buf = t & 1;
        cpa_wait<0>();
        __syncthreads();

        if (t + 1 < ntiles) stageA(t + 1, buf ^ 1);

        float ccv[16];
        {
            int sbase = t * 32 + hf * 16;
            #pragma unroll
            for (int j = 0; j < 16; j++) {
                int s = sbase + j;
                float v = 0.0f;
                if (s < count) {
                    int e = sList[s];
                    v = child_c[((size_t)(b0 + (e >> 8)) * NN + (e & 63)) * HH + g0 + gcol];
                }
                ccv[j] = v;
            }
        }

        float d[2][2][4];
        #pragma unroll
        for (int mt = 0; mt < 2; mt++)
            #pragma unroll
            for (int nt = 0; nt < 2; nt++)
                #pragma unroll
                for (int q = 0; q < 4; q++) d[mt][nt][q] = 0.0f;
        {
            const uint32_t ahb = smb + AB_OFF(buf);
            const uint32_t blb = smb + BL_OFF;
            int brow = warp * 16 + ((tIdx & 2) ? 8 : 0) + rsub;
            #pragma unroll
            for (int kt = 0; kt < 8; kt++) {
                int kk = kt * 16;
                int kfrag = kk + ((tIdx & 1) ? 8 : 0);
                uint32_t areg[2][4], blreg[4];
                #pragma unroll
                for (int mt = 0; mt < 2; mt++) {
                    int row = mt * 16 + ((tIdx & 1) ? 8 : 0) + rsub;
                    int col = kk + ((tIdx & 2) ? 8 : 0);
                    ldsm4(areg[mt], ahb + (uint32_t)(row * BSTR + col) * 2u);
                }
                ldsm4(blreg, blb + (uint32_t)(brow * BSTR + kfrag) * 2u);
                #pragma unroll
                for (int mt = 0; mt < 2; mt++)
                    #pragma unroll
                    for (int nt = 0; nt < 2; nt++) {
                        mma16816h(d[mt][nt], areg[mt], &bhreg[kt][nt * 2]);
                        mma16816h(d[mt][nt], areg[mt], &blreg[nt * 2]);
                    }
            }
        }

        {
            float* F = (float*)(dsm + F_OFF);
            int arow = lane >> 2, acol = (lane & 3) * 2;
            #pragma unroll
            for (int mt = 0; mt < 2; mt++)
                #pragma unroll
                for (int nt = 0; nt < 2; nt++) {
                    int col = warp * 16 + nt * 8 + acol;
                    F[(mt * 16 + arow) * FSTR + col]         = d[mt][nt][0];
                    F[(mt * 16 + arow) * FSTR + col + 1]     = d[mt][nt][1];
                    F[(mt * 16 + arow + 8) * FSTR + col]     = d[mt][nt][2];
                    F[(mt * 16 + arow + 8) * FSTR + col + 1] = d[mt][nt][3];
                }
        }
        __syncthreads();

        {
            const float* F = (const float*)(dsm + F_OFF);
            int sbase = t * 32 + hf * 16;
            int smax = min(16, count - sbase);
            for (int j = 0; j < smax; j++) {
                int e = sList[sbase + j];
                int bl = e >> 8;
                float dcy = ((e >> 6) & 1) ? VDECAY : 1.0f;
                float Fv = F[(hf * 16 + j) * FSTR + gcol];
                shCS[hf][bl][gcol] += (Fv * dcy + bfk) * (ccv[j] * dcy);
            }
        }
    }

    {
        int slot = r * 2 + khalf;
        __syncthreads();
        for (int i = tid; i < 16 * 128; i += 256) {
            int bl = i >> 7, g = i & 127;
            g_csum6[((size_t)slot * BB + b0 + bl) * HH + g0 + g] =
                shCS[0][bl][g] + shCS[1][bl][g];
        }
    }
}

// ---------------- gates_mma: HMMA gate GEMM, 3-term split ----------------
// grid (128, 3): x = batch tile (32), y = gate. block 256 = 8 warps.
// dyn smem 214016: A_HI @0 (33280), A_LO @33280, B @66560: buf*73728 + hl*36864
#define ASTR 520
#define GA_LO 33280
#define GB(buf, hl) (66560 + (buf) * 73728 + (hl) * 36864)
#define GBSTR 72
#define GG_DYN 214016

__global__ __launch_bounds__(256) void gates_mma() {
    extern __shared__ char dsm[];
    const int tid = threadIdx.x, lane = tid & 31, warp = tid >> 5;
    const int b0 = blockIdx.x * 32, gate = blockIdx.y;
    const uint32_t smb = smem_u32(dsm);
    const int tIdx = lane >> 3, rsub = lane & 7;

    // stage A (comb hi+lo, 32 batches x 512 k) — one group with B chunk 0
    for (int i = tid; i < 4096; i += 256) {
        int hl = i >> 11, j = i & 2047;
        int s = j >> 6, q = j & 63;
        const __half* src = (hl ? g_combL : g_combH) + (size_t)(b0 + s) * 512 + q * 8;
        cpa16(dsm + hl * GA_LO + (s * ASTR + q * 8) * 2, src);
    }

    auto stageB = [&](int kc, int buf) {
        for (int i = tid; i < 4096; i += 256) {
            int hl = i >> 11, j = i & 2047;
            int n = j >> 3, q = j & 7;
            const __half* src = (hl ? g_WgL : g_WgH) +
                ((size_t)gate * 256 + n) * 512 + kc * 64 + q * 8;
            cpa16(dsm + GB(buf, hl) + (n * GBSTR + q * 8) * 2, src);
        }
        CPA_COMMIT();
    };

    stageB(0, 0);   // commits A + B0 together

    float d[2][4][4];
    #pragma unroll
    for (int mt = 0; mt < 2; mt++)
        #pragma unroll
        for (int nq = 0; nq < 4; nq++)
            #pragma unroll
            for (int q = 0; q < 4; q++) d[mt][nq][q] = 0.0f;

    #pragma unroll 1
    for (int kc = 0; kc < 8; kc++) {
        int buf = kc & 1;
        if (kc < 7) stageB(kc + 1, buf ^ 1);
        else CPA_COMMIT();
        cpa_wait<1>();
        __syncthreads();

        #pragma unroll
        for (int ks = 0; ks < 4; ks++) {
            int kk = ks * 16;
            uint32_t ah[2][4], al[2][4], bh[2][4], bl[2][4];
            #pragma unroll
            for (int mt = 0; mt < 2; mt++) {
                int row = mt * 16 + ((tIdx & 1) ? 8 : 0) + rsub;
                int col = kc * 64 + kk + ((tIdx & 2) ? 8 : 0);
                ldsm4(ah[mt], smb + (uint32_t)(row * ASTR + col) * 2u);
                ldsm4(al[mt], smb + GA_LO + (uint32_t)(row * ASTR + col) * 2u);
            }
            #pragma unroll
            for (int ng = 0; ng < 2; ng++) {
                int n = warp * 32 + ng * 16 + ((tIdx & 2) ? 8 : 0) + rsub;
                int k = kk + ((tIdx & 1) ? 8 : 0);
                ldsm4(bh[ng], smb + GB(buf, 0) + (uint32_t)(n * GBSTR + k) * 2u);
                ldsm4(bl[ng], smb + GB(buf, 1) + (uint32_t)(n * GBSTR + k) * 2u);
            }
            #pragma unroll
            for (int mt = 0; mt < 2; mt++)
                #pragma unroll
                for (int ng = 0; ng < 2; ng++)
                    #pragma unroll
                    for (int sub = 0; sub < 2; sub++) {
                        float* dd = d[mt][ng * 2 + sub];
                        mma16816h(dd, ah[mt], &bh[ng][sub * 2]);
                        mma16816h(dd, al[mt], &bh[ng][sub * 2]);
                        mma16816h(dd, ah[mt], &bl[ng][sub * 2]);
                    }
        }
        __syncthreads();
    }
    cpa_wait<0>();

    // write preacts
    {
        int arow = lane >> 2, acol = (lane & 3) * 2;
        #pragma unroll
        for (int mt = 0; mt < 2; mt++)
            #pragma unroll
            for (int nq = 0; nq < 4; nq++) {
                int gcol = warp * 32 + nq * 8 + acol;
                int bA = b0 + mt * 16 + arow;
                float* p = g_pre + ((size_t)gate * BB) * HH;
                *(float2*)&p[(size_t)bA * HH + gcol] = make_float2(d[mt][nq][0], d[mt][nq][1]);
                *(float2*)&p[(size_t)(bA + 8) * HH + gcol] = make_float2(d[mt][nq][2], d[mt][nq][3]);
            }
    }
}

// ---------------- epilogue: biases + csum + activations ----------------
__global__ __launch_bounds__(256) void epi_kernel(
    const float* __restrict__ b_i, const float* __restrict__ b_o,
    const float* __restrict__ b_u, float* __restrict__ out)
{
    const int b = blockIdx.x, g = threadIdx.x;
    size_t idx = (size_t)b * HH + g;
    float cs = 0.0f;
    #pragma unroll
    for (int slot = 0; slot < 6; slot++)
        cs += g_csum6[(size_t)slot * BB * HH + idx];
    float pi = g_pre[idx]                      + b_i[g];
    float po = g_pre[(size_t)BB * HH + idx]    + b_o[g];
    float pu = g_pre[(size_t)2 * BB * HH + idx] + b_u[g];
    float iv = 1.0f / (1.0f + expf(-pi));
    float ov = 1.0f / (1.0f + expf(-po));
    float uv = tanhf(pu);
    float cv = fmaf(iv, uv, cs);
    float hv = ov * tanhf(cv);
    out[idx]                      = hv;   // h first
    out[(size_t)BB * HH + idx]    = cv;   // then c
}

// ---------------- launch ----------------
extern "C" void kernel_launch(void* const* d_in, const int* in_sizes, int n_in,
                              void* d_out, int out_size) {
    const float* input_vec = (const float*)d_in[0];
    const float* child_h   = (const float*)d_in[1];
    const float* child_c   = (const float*)d_in[2];
    const int*   rid       = (const int*)d_in[3];
    const int*   vmask     = (const int*)d_in[4];
    const float* rel_emb   = (const float*)d_in[5];
    const float* W_i = (const float*)d_in[6];
    const float* b_i = (const float*)d_in[7];
    const float* W_f = (const float*)d_in[8];
    const float* b_f = (const float*)d_in[9];
    const float* W_o = (const float*)d_in[10];
    const float* b_o = (const float*)d_in[11];
    const float* W_u = (const float*)d_in[12];
    const float* b_u = (const float*)d_in[13];
    const float* w_att = (const float*)d_in[14];
    const float* b_att = (const float*)d_in[15];
    float* out = (float*)d_out;

    cudaFuncSetAttribute(fgemm_mma, cudaFuncAttributeMaxDynamicSharedMemorySize, FG_DYN);
    cudaFuncSetAttribute(gates_mma, cudaFuncAttributeMaxDynamicSharedMemorySize, GG_DYN);

    prep_kernel<<<2304, 256>>>(W_i, W_o, W_u, W_f);
    attn_kernel<<<BB, 256>>>(input_vec, child_h, rid, vmask, rel_emb, w_att, b_att);
    dim3 fg(BB / 16, RR, 4);
    fgemm_mma<<<fg, 256, FG_DYN>>>(child_c, rid, vmask, b_f);
    dim3 gg(BB / 32, 3);
    gates_mma<<<gg, 256, GG_DYN>>>();
    epi_kernel<<<BB, 256>>>(b_i, b_o, b_u, out);
}